// round 5
// baseline (speedup 1.0000x reference)
#include <cuda_runtime.h>
#include <math.h>
#include <stdint.h>

#define MS 4096            // square: M == N == 4096
#define RD 16
#define NP 136             // 16*17/2 symmetric pairs
#define KSPLIT 4           // split-K for gram
#define SPL 8              // split factor for col-mode res/t partials
#define TS 512
#define EPSR 1e-5f
#define AST 36             // smem row stride (floats) for mma tiles

// ---------------- scratch (~18 MB of device globals) ----------------
__device__ float g_Apart[(size_t)KSPLIT * NP * MS];  // 8.9 MB gram partials
__device__ float g_Ainv[(size_t)MS * RD * RD];       // 4.0 MB
__device__ float g_Pt[(size_t)NP * MS];              // 2.2 MB Pt [p][s] (tf32 values)
__device__ float g_U[MS * RD];
__device__ float g_Vt[MS * RD];                      // V transposed: [n][r]
__device__ float g_tpart[(size_t)SPL * MS * RD];     // 2.0 MB
__device__ float g_ssq[MS];
__device__ float g_ssqpart[SPL * MS];
__device__ float g_cntpart[SPL * MS];
__device__ float g_cntc[MS];
__device__ float g_cntr[MS];
__device__ float g_sig[MS];
__device__ float g_coef[4];                          // c, lamda, mu, alpha

// ---------------- setup: copy U, transpose V ----------------
__global__ void k_setup(const float* __restrict__ U, const float* __restrict__ V) {
    int tid = blockIdx.x * 256 + threadIdx.x;
    g_U[tid] = U[tid];
    int n = tid >> 4, r = tid & 15;
    g_Vt[tid] = V[r * MS + n];
}

// ---------------- counts ----------------
__global__ void k_cnt_col(const float* __restrict__ X) {
    int j = blockIdx.x * 256 + threadIdx.x;
    int s0 = blockIdx.y * TS;
    float c = 0.f;
    for (int s = 0; s < TS; s++)
        c += (X[(size_t)(s0 + s) * MS + j] != 0.f) ? 1.f : 0.f;
    g_cntpart[blockIdx.y * MS + j] = c;
}
__global__ void k_cnt_fin() {
    int j = blockIdx.x * 256 + threadIdx.x;
    float c = 0.f;
    #pragma unroll
    for (int sp = 0; sp < SPL; sp++) c += g_cntpart[sp * MS + j];
    g_cntc[j] = c;
}
__global__ void k_cnt_row(const float* __restrict__ X) {
    int wid = threadIdx.x >> 5, lane = threadIdx.x & 31;
    int i = blockIdx.x * 8 + wid;
    float c = 0.f;
    for (int s = lane; s < MS; s += 32)
        c += (X[(size_t)i * MS + s] != 0.f) ? 1.f : 0.f;
    #pragma unroll
    for (int off = 16; off; off >>= 1) c += __shfl_xor_sync(~0u, c, off);
    if (lane == 0) g_cntr[i] = c;
}

// ---------------- P build (+ per-layer coefficients when do_coef) ----------------
__global__ void k_P(int mode, int do_coef, const float* __restrict__ cc,
                    const float* __restrict__ lam, const float* __restrict__ mu, int layer) {
    if (do_coef && blockIdx.x == 0 && threadIdx.x == 0) {
        double cl = (double)cc[layer];
        double chi1 = erf(sqrt(cl));
        double y = 0.5 * cl * cl;
        double chi3 = erf(sqrt(y)) - 2.0 * sqrt(y) * exp(-y) / sqrt(3.14159265358979323846);
        double alpha = cl * (1.0 - chi1) + 0.5 * chi3;
        g_coef[0] = (float)cl;
        g_coef[1] = lam[layer];
        g_coef[2] = mu[layer];
        g_coef[3] = (float)alpha;
    }
    int s = blockIdx.x * 256 + threadIdx.x;
    const float* F = mode ? g_Vt : g_U;
    float u[RD];
    const float4* f4 = (const float4*)(F + s * RD);
    #pragma unroll
    for (int q = 0; q < 4; q++) {
        float4 v = f4[q];
        u[q * 4 + 0] = v.x; u[q * 4 + 1] = v.y; u[q * 4 + 2] = v.z; u[q * 4 + 3] = v.w;
    }
    #pragma unroll
    for (int r = 0; r < RD; r++) {
        #pragma unroll
        for (int c2 = 0; c2 <= r; c2++) {
            float v = u[r] * u[c2];
            uint32_t t;
            asm("cvt.rna.tf32.f32 %0, %1;" : "=r"(t) : "f"(v));
            g_Pt[(size_t)(r * (r + 1) / 2 + c2) * MS + s] = __uint_as_float(t);
        }
    }
}

// ---------------- tf32 mma.sync Gram ----------------
__device__ __forceinline__ void mma_tf32(float* c, const uint32_t* a, uint32_t b0, uint32_t b1) {
    asm volatile(
        "mma.sync.aligned.m16n8k8.row.col.f32.tf32.tf32.f32 "
        "{%0,%1,%2,%3}, {%4,%5,%6,%7}, {%8,%9}, {%0,%1,%2,%3};"
        : "+f"(c[0]), "+f"(c[1]), "+f"(c[2]), "+f"(c[3])
        : "r"(a[0]), "r"(a[1]), "r"(a[2]), "r"(a[3]), "r"(b0), "r"(b1));
}

__global__ __launch_bounds__(256, 2) void k_gram(const float* __restrict__ X, int mode) {
    __shared__ float As[128 * AST];
    __shared__ float Bs[NP * AST];
    int tx = threadIdx.x, wid = tx >> 5, lane = tx & 31;
    int g = lane >> 2, tig = lane & 3;
    int wm = wid & 3, wn = wid >> 2;
    int j0 = blockIdx.x * 128;
    int sbase = blockIdx.y * (MS / KSPLIT);
    int nbase = wn * 9;
    int ntiles = wn ? 8 : 9;

    float c[2][9][4];
    #pragma unroll
    for (int tm = 0; tm < 2; tm++)
        #pragma unroll
        for (int nt = 0; nt < 9; nt++)
            #pragma unroll
            for (int q = 0; q < 4; q++) c[tm][nt][q] = 0.f;

    for (int ch = 0; ch < (MS / KSPLIT) / 32; ch++) {
        int s0 = sbase + ch * 32;
        __syncthreads();
        if (mode == 0) {
            #pragma unroll
            for (int k = 0; k < 16; k++) {
                int e = tx + k * 256; int jj = e & 127, s = e >> 7;
                float x = X[(size_t)(s0 + s) * MS + j0 + jj];
                As[jj * AST + s] = (x != 0.f) ? 1.f : 0.f;
            }
        } else {
            #pragma unroll
            for (int k = 0; k < 16; k++) {
                int e = tx + k * 256; int ii = e >> 5, s = e & 31;
                float x = X[(size_t)(j0 + ii) * MS + s0 + s];
                As[ii * AST + s] = (x != 0.f) ? 1.f : 0.f;
            }
        }
        #pragma unroll
        for (int k = 0; k < 17; k++) {
            int e = tx + k * 256; int p = e >> 5, s = e & 31;
            Bs[p * AST + s] = g_Pt[(size_t)p * MS + s0 + s];
        }
        __syncthreads();

        #pragma unroll
        for (int t = 0; t < 4; t++) {
            int kc = t * 8;
            uint32_t a[2][4];
            #pragma unroll
            for (int tm = 0; tm < 2; tm++) {
                int r0 = wm * 32 + tm * 16;
                a[tm][0] = __float_as_uint(As[(r0 + g) * AST + kc + tig]);
                a[tm][1] = __float_as_uint(As[(r0 + g + 8) * AST + kc + tig]);
                a[tm][2] = __float_as_uint(As[(r0 + g) * AST + kc + tig + 4]);
                a[tm][3] = __float_as_uint(As[(r0 + g + 8) * AST + kc + tig + 4]);
            }
            #pragma unroll
            for (int nt = 0; nt < 9; nt++) {
                if (nt < ntiles) {
                    int n0 = (nbase + nt) * 8;
                    uint32_t b0 = __float_as_uint(Bs[(n0 + g) * AST + kc + tig]);
                    uint32_t b1 = __float_as_uint(Bs[(n0 + g) * AST + kc + tig + 4]);
                    mma_tf32(c[0][nt], a[0], b0, b1);
                    mma_tf32(c[1][nt], a[1], b0, b1);
                }
            }
        }
    }

    size_t base = (size_t)blockIdx.y * NP * MS;
    #pragma unroll
    for (int tm = 0; tm < 2; tm++) {
        int row = j0 + wm * 32 + tm * 16 + g;
        #pragma unroll
        for (int nt = 0; nt < 9; nt++) {
            if (nt < ntiles) {
                int p0 = (nbase + nt) * 8 + 2 * tig;
                g_Apart[base + (size_t)p0 * MS + row]           = c[tm][nt][0];
                g_Apart[base + (size_t)(p0 + 1) * MS + row]     = c[tm][nt][1];
                g_Apart[base + (size_t)p0 * MS + row + 8]       = c[tm][nt][2];
                g_Apart[base + (size_t)(p0 + 1) * MS + row + 8] = c[tm][nt][3];
            }
        }
    }
}

// ---------------- reduce partials + ridge, invert 16x16; also init sigma ----------------
__global__ void k_inv(const float* __restrict__ sigma) {
    __shared__ float Mm[16][33];
    int t = threadIdx.x;
    int r = t >> 4, cc = t & 15;
    int i = blockIdx.x;
    if (t == 0) g_sig[i] = sigma[0];

    int rr = max(r, cc), cs = min(r, cc);
    int p = rr * (rr + 1) / 2 + cs;
    float sum = 0.f;
    #pragma unroll
    for (int sp = 0; sp < KSPLIT; sp++)
        sum += g_Apart[(size_t)sp * NP * MS + (size_t)p * MS + i];
    if (r == cc) sum += EPSR;
    Mm[r][cc] = sum;
    Mm[r][cc + 16] = (r == cc) ? 1.f : 0.f;
    __syncthreads();

    for (int k = 0; k < 16; k++) {
        float piv = Mm[k][k];
        __syncthreads();
        if (r == k) {
            float pivinv = 1.f / piv;
            Mm[k][cc] *= pivinv;
            Mm[k][cc + 16] *= pivinv;
        }
        __syncthreads();
        float f = Mm[r][k];
        float mk1 = Mm[k][cc];
        float mk2 = Mm[k][cc + 16];
        __syncthreads();
        if (r != k) {
            Mm[r][cc] -= f * mk1;
            Mm[r][cc + 16] -= f * mk2;
        }
        __syncthreads();
    }
    g_Ainv[(size_t)i * 256 + r * 16 + cc] = Mm[r][cc + 16];
}

// ================= col-mode (2 columns per thread) =================
__global__ __launch_bounds__(256) void k_res_col(const float* __restrict__ X) {
    __shared__ float sF[TS * RD];
    int tx = threadIdx.x;
    int j = blockIdx.x * 512 + tx * 2;
    int s0 = blockIdx.y * TS;
    #pragma unroll
    for (int k = 0; k < 32; k++)
        sF[tx + k * 256] = g_U[s0 * RD + tx + k * 256];
    float b0[RD], b1[RD];
    #pragma unroll
    for (int q = 0; q < 4; q++) {
        float4 v0 = ((const float4*)(g_Vt + j * RD))[q];
        float4 v1 = ((const float4*)(g_Vt + (j + 1) * RD))[q];
        b0[q*4+0]=v0.x; b0[q*4+1]=v0.y; b0[q*4+2]=v0.z; b0[q*4+3]=v0.w;
        b1[q*4+0]=v1.x; b1[q*4+1]=v1.y; b1[q*4+2]=v1.z; b1[q*4+3]=v1.w;
    }
    float cl = g_coef[0];
    float is0 = 1.f / g_sig[j], is1 = 1.f / g_sig[j + 1];
    __syncthreads();

    float a0 = 0.f, a1 = 0.f;
    for (int s = 0; s < TS; s++) {
        float2 d = *(const float2*)&X[(size_t)(s0 + s) * MS + j];
        float dot0 = 0.f, dot1 = 0.f;
        #pragma unroll
        for (int r = 0; r < RD; r++) {
            float f = sF[s * RD + r];
            dot0 += f * b0[r];
            dot1 += f * b1[r];
        }
        float rv0 = (d.x != 0.f) ? (d.x - dot0) : 0.f;
        float rv1 = (d.y != 0.f) ? (d.y - dot1) : 0.f;
        float p0 = fminf(fmaxf(rv0 * is0, -cl), cl);
        float p1 = fminf(fmaxf(rv1 * is1, -cl), cl);
        a0 += p0 * p0;
        a1 += p1 * p1;
    }
    *(float2*)&g_ssqpart[blockIdx.y * MS + j] = make_float2(a0, a1);
}

// t pass with fused sigma computation
__global__ __launch_bounds__(256) void k_t_col(const float* __restrict__ X) {
    __shared__ float sF[TS * RD];
    int tx = threadIdx.x;
    int j = blockIdx.x * 512 + tx * 2;
    int s0 = blockIdx.y * TS;
    #pragma unroll
    for (int k = 0; k < 32; k++)
        sF[tx + k * 256] = g_U[s0 * RD + tx + k * 256];
    float b0[RD], b1[RD];
    #pragma unroll
    for (int q = 0; q < 4; q++) {
        float4 v0 = ((const float4*)(g_Vt + j * RD))[q];
        float4 v1 = ((const float4*)(g_Vt + (j + 1) * RD))[q];
        b0[q*4+0]=v0.x; b0[q*4+1]=v0.y; b0[q*4+2]=v0.z; b0[q*4+3]=v0.w;
        b1[q*4+0]=v1.x; b1[q*4+1]=v1.y; b1[q*4+2]=v1.z; b1[q*4+3]=v1.w;
    }
    // sigma from ssq partials
    float ss0 = 0.f, ss1 = 0.f;
    #pragma unroll
    for (int sp = 0; sp < SPL; sp++) {
        float2 v = *(const float2*)&g_ssqpart[sp * MS + j];
        ss0 += v.x; ss1 += v.y;
    }
    float cl = g_coef[0], ll = g_coef[1], alpha = g_coef[3];
    float sg0 = ll * sqrtf(ss0) / sqrtf(2.f * g_cntc[j] * alpha);
    float sg1 = ll * sqrtf(ss1) / sqrtf(2.f * g_cntc[j + 1] * alpha);
    if (blockIdx.y == 0) {
        g_sig[j] = sg0;
        g_sig[j + 1] = sg1;
    }
    float th0 = cl * sg0, th1 = cl * sg1;
    __syncthreads();

    float acc0[RD], acc1[RD];
    #pragma unroll
    for (int r = 0; r < RD; r++) { acc0[r] = 0.f; acc1[r] = 0.f; }
    for (int s = 0; s < TS; s++) {
        float2 d = *(const float2*)&X[(size_t)(s0 + s) * MS + j];
        float dot0 = 0.f, dot1 = 0.f;
        #pragma unroll
        for (int r = 0; r < RD; r++) {
            float f = sF[s * RD + r];
            dot0 += f * b0[r];
            dot1 += f * b1[r];
        }
        float rv0 = (d.x != 0.f) ? (d.x - dot0) : 0.f;
        float rv1 = (d.y != 0.f) ? (d.y - dot1) : 0.f;
        float p0 = fminf(fmaxf(rv0, -th0), th0);
        float p1 = fminf(fmaxf(rv1, -th1), th1);
        #pragma unroll
        for (int r = 0; r < RD; r++) {
            float f = sF[s * RD + r];
            acc0[r] += f * p0;
            acc1[r] += f * p1;
        }
    }
    float* o0 = g_tpart + ((size_t)blockIdx.y * MS + j) * RD;
    #pragma unroll
    for (int q = 0; q < 4; q++) {
        ((float4*)o0)[q]      = make_float4(acc0[q*4], acc0[q*4+1], acc0[q*4+2], acc0[q*4+3]);
        ((float4*)(o0+RD))[q] = make_float4(acc1[q*4], acc1[q*4+1], acc1[q*4+2], acc1[q*4+3]);
    }
}

// fused reduce-t + update (col): Vt[i] += mu * Ainv[i] @ t[i]
__global__ void k_updcol() {
    __shared__ float ts[256];
    int tx = threadIdx.x;
    int tid = blockIdx.x * 256 + tx;
    int i = tid >> 4, r = tid & 15;
    float s = 0.f;
    #pragma unroll
    for (int sp = 0; sp < SPL; sp++)
        s += g_tpart[((size_t)sp * MS + i) * RD + r];
    ts[tx] = s;
    __syncthreads();
    const float* Ai = g_Ainv + (size_t)i * 256 + r * 16;
    const float* ti = ts + (tx & ~15);
    float delta = 0.f;
    #pragma unroll
    for (int q = 0; q < RD; q++) delta += Ai[q] * ti[q];
    g_Vt[tid] += g_coef[2] * delta;
}

// ================= row-mode (warp per row) =================
__global__ __launch_bounds__(256) void k_res_row(const float* __restrict__ X) {
    __shared__ float sV[RD * 513];
    int tx = threadIdx.x, wid = tx >> 5, lane = tx & 31;
    int i = blockIdx.x * 8 + wid;
    float b[RD];
    #pragma unroll
    for (int r = 0; r < RD; r++) b[r] = g_U[i * RD + r];
    float cl = g_coef[0];
    float inv_sig = 1.f / g_sig[i];

    float acc = 0.f;
    for (int t = 0; t < 8; t++) {
        __syncthreads();
        #pragma unroll
        for (int k = 0; k < 32; k++) {
            int idx = tx + k * 256;
            int s = idx >> 4, r = idx & 15;
            sV[r * 513 + s] = g_Vt[t * 8192 + idx];
        }
        __syncthreads();
        #pragma unroll 2
        for (int k = 0; k < 16; k++) {
            int s = lane + k * 32;
            float d = X[(size_t)i * MS + t * TS + s];
            float dot = 0.f;
            #pragma unroll
            for (int r = 0; r < RD; r++) dot += sV[r * 513 + s] * b[r];
            float rv = (d != 0.f) ? (d - dot) : 0.f;
            float ps = fminf(fmaxf(rv * inv_sig, -cl), cl);
            acc += ps * ps;
        }
    }
    #pragma unroll
    for (int off = 16; off; off >>= 1) acc += __shfl_xor_sync(~0u, acc, off);
    if (lane == 0) g_ssq[i] = acc;
}

// t pass with fused sigma + fused B update (row)
__global__ __launch_bounds__(256) void k_t_row(const float* __restrict__ X) {
    __shared__ float sV[RD * 513];
    int tx = threadIdx.x, wid = tx >> 5, lane = tx & 31;
    int i = blockIdx.x * 8 + wid;
    float b[RD];
    #pragma unroll
    for (int r = 0; r < RD; r++) b[r] = g_U[i * RD + r];
    float cl = g_coef[0], ll = g_coef[1], alpha = g_coef[3];
    float sg = ll * sqrtf(g_ssq[i]) / sqrtf(2.f * g_cntr[i] * alpha);
    float thr = cl * sg;

    float acc[RD];
    #pragma unroll
    for (int r = 0; r < RD; r++) acc[r] = 0.f;
    for (int t = 0; t < 8; t++) {
        __syncthreads();
        #pragma unroll
        for (int k = 0; k < 32; k++) {
            int idx = tx + k * 256;
            int s = idx >> 4, r = idx & 15;
            sV[r * 513 + s] = g_Vt[t * 8192 + idx];
        }
        __syncthreads();
        #pragma unroll 2
        for (int k = 0; k < 16; k++) {
            int s = lane + k * 32;
            float d = X[(size_t)i * MS + t * TS + s];
            float dot = 0.f;
            #pragma unroll
            for (int r = 0; r < RD; r++) dot += sV[r * 513 + s] * b[r];
            float rv = (d != 0.f) ? (d - dot) : 0.f;
            float pc = fminf(fmaxf(rv, -thr), thr);
            #pragma unroll
            for (int r = 0; r < RD; r++) acc[r] += sV[r * 513 + s] * pc;
        }
    }
    // butterfly: after this every lane holds the full t[16]
    #pragma unroll
    for (int r = 0; r < RD; r++) {
        #pragma unroll
        for (int off = 16; off; off >>= 1)
            acc[r] += __shfl_xor_sync(~0u, acc[r], off);
    }
    if (lane == 0) g_sig[i] = sg;
    // fused update: lanes 0..15 apply delta = Ainv[i] row(lane) . t
    if (lane < 16) {
        const float4* Ai = (const float4*)(g_Ainv + (size_t)i * 256 + lane * 16);
        float delta = 0.f;
        #pragma unroll
        for (int q = 0; q < 4; q++) {
            float4 a4 = Ai[q];
            delta += a4.x * acc[q*4] + a4.y * acc[q*4+1] + a4.z * acc[q*4+2] + a4.w * acc[q*4+3];
        }
        g_U[i * RD + lane] += g_coef[2] * delta;
    }
}

// ---------------- final out = U @ V ----------------
__global__ void k_out(float* __restrict__ out) {
    __shared__ float sU[64 * RD];
    int tx = threadIdx.x;
    int n = blockIdx.x * 256 + tx;
    int m0 = blockIdx.y * 64;
    #pragma unroll
    for (int k = 0; k < 4; k++)
        sU[tx + k * 256] = g_U[m0 * RD + tx + k * 256];
    float v[RD];
    #pragma unroll
    for (int r = 0; r < RD; r++) v[r] = g_Vt[n * RD + r];
    __syncthreads();
    for (int j = 0; j < 64; j++) {
        float dot = 0.f;
        #pragma unroll
        for (int r = 0; r < RD; r++) dot += sU[j * RD + r] * v[r];
        out[(size_t)(m0 + j) * MS + n] = dot;
    }
}

// ---------------- orchestration ----------------
extern "C" void kernel_launch(void* const* d_in, const int* in_sizes, int n_in,
                              void* d_out, int out_size) {
    const float* U_in  = (const float*)d_in[0];
    const float* V_in  = (const float*)d_in[1];
    const float* X     = (const float*)d_in[2];
    const float* c_in  = (const float*)d_in[3];
    const float* l_in  = (const float*)d_in[4];
    const float* m_in  = (const float*)d_in[5];
    const float* sg_in = (const float*)d_in[6];
    float* out = (float*)d_out;

    dim3 b256(256);
    dim3 gcol(8, SPL);          // 2 cols/thread
    dim3 gcnt(16, SPL);
    dim3 ggram(32, KSPLIT);

    k_setup<<<256, 256>>>(U_in, V_in);
    k_cnt_col<<<gcnt, b256>>>(X);
    k_cnt_fin<<<16, 256>>>();
    k_cnt_row<<<512, 256>>>(X);

    for (int layer = 0; layer < 3; layer++) {
        // ---- V step (col-mode) ----
        k_P<<<16, 256>>>(0, 1, c_in, l_in, m_in, layer);
        k_gram<<<ggram, b256>>>(X, 0);
        k_inv<<<4096, 256>>>(sg_in);
        for (int it = 0; it < 2; it++) {
            k_res_col<<<gcol, b256>>>(X);
            k_t_col<<<gcol, b256>>>(X);
            k_updcol<<<256, 256>>>();
        }

        // ---- U step (row-mode) ----
        k_P<<<16, 256>>>(1, 0, c_in, l_in, m_in, layer);
        k_gram<<<ggram, b256>>>(X, 1);
        k_inv<<<4096, 256>>>(sg_in);
        for (int it = 0; it < 2; it++) {
            k_res_row<<<512, 256>>>(X);
            k_t_row<<<512, 256>>>(X);
        }
    }

    k_out<<<dim3(16, 64), 256>>>(out);
}

// round 6
// speedup vs baseline: 1.3625x; 1.3625x over previous
#include <cuda_runtime.h>
#include <math.h>
#include <stdint.h>

#define MS 4096            // square: M == N == 4096
#define RD 16
#define NP 136             // 16*17/2 symmetric pairs
#define KSPLIT 4           // split-K for gram
#define SPL 16             // split factor for col-mode res/t partials
#define TS 256             // samples per col-mode split (4096/SPL)
#define EPSR 1e-5f
#define AST 36             // smem row stride (floats) for mma tiles

// ---------------- scratch (~20 MB of device globals) ----------------
__device__ float g_Apart[(size_t)KSPLIT * NP * MS];  // 8.9 MB gram partials
__device__ float g_Ainv[(size_t)MS * RD * RD];       // 4.0 MB
__device__ float g_Pt[(size_t)NP * MS];              // 2.2 MB Pt [p][s] (tf32 values)
__device__ float g_U[MS * RD];
__device__ float g_Vt[MS * RD];                      // V transposed: [n][r]
__device__ float g_tpart[(size_t)SPL * MS * RD];     // 4.0 MB
__device__ float g_ssq[MS];
__device__ float g_ssqpart[SPL * MS];
__device__ float g_cntpart[SPL * MS];
__device__ float g_cntc[MS];
__device__ float g_cntr[MS];
__device__ float g_sig[MS];
__device__ float g_coef[4];                          // c, lamda, mu, alpha

// ---------------- setup: copy U, transpose V ----------------
__global__ void k_setup(const float* __restrict__ U, const float* __restrict__ V) {
    int tid = blockIdx.x * 256 + threadIdx.x;
    g_U[tid] = U[tid];
    int n = tid >> 4, r = tid & 15;
    g_Vt[tid] = V[r * MS + n];
}

// ---------------- counts ----------------
__global__ void k_cnt_col(const float* __restrict__ X) {
    int j = blockIdx.x * 256 + threadIdx.x;
    int s0 = blockIdx.y * TS;
    float c = 0.f;
    for (int s = 0; s < TS; s++)
        c += (X[(size_t)(s0 + s) * MS + j] != 0.f) ? 1.f : 0.f;
    g_cntpart[blockIdx.y * MS + j] = c;
}
__global__ void k_cnt_fin() {
    int j = blockIdx.x * 256 + threadIdx.x;
    float c = 0.f;
    #pragma unroll
    for (int sp = 0; sp < SPL; sp++) c += g_cntpart[sp * MS + j];
    g_cntc[j] = c;
}
__global__ void k_cnt_row(const float* __restrict__ X) {
    int wid = threadIdx.x >> 5, lane = threadIdx.x & 31;
    int i = blockIdx.x * 8 + wid;
    float c = 0.f;
    for (int s = lane; s < MS; s += 32)
        c += (X[(size_t)i * MS + s] != 0.f) ? 1.f : 0.f;
    #pragma unroll
    for (int off = 16; off; off >>= 1) c += __shfl_xor_sync(~0u, c, off);
    if (lane == 0) g_cntr[i] = c;
}

// ---------------- P build (+ per-layer coefficients when do_coef) ----------------
__global__ void k_P(int mode, int do_coef, const float* __restrict__ cc,
                    const float* __restrict__ lam, const float* __restrict__ mu, int layer) {
    if (do_coef && blockIdx.x == 0 && threadIdx.x == 0) {
        double cl = (double)cc[layer];
        double chi1 = erf(sqrt(cl));
        double y = 0.5 * cl * cl;
        double chi3 = erf(sqrt(y)) - 2.0 * sqrt(y) * exp(-y) / sqrt(3.14159265358979323846);
        double alpha = cl * (1.0 - chi1) + 0.5 * chi3;
        g_coef[0] = (float)cl;
        g_coef[1] = lam[layer];
        g_coef[2] = mu[layer];
        g_coef[3] = (float)alpha;
    }
    int s = blockIdx.x * 256 + threadIdx.x;
    const float* F = mode ? g_Vt : g_U;
    float u[RD];
    const float4* f4 = (const float4*)(F + s * RD);
    #pragma unroll
    for (int q = 0; q < 4; q++) {
        float4 v = f4[q];
        u[q * 4 + 0] = v.x; u[q * 4 + 1] = v.y; u[q * 4 + 2] = v.z; u[q * 4 + 3] = v.w;
    }
    #pragma unroll
    for (int r = 0; r < RD; r++) {
        #pragma unroll
        for (int c2 = 0; c2 <= r; c2++) {
            float v = u[r] * u[c2];
            uint32_t t;
            asm("cvt.rna.tf32.f32 %0, %1;" : "=r"(t) : "f"(v));
            g_Pt[(size_t)(r * (r + 1) / 2 + c2) * MS + s] = __uint_as_float(t);
        }
    }
}

// ---------------- tf32 mma.sync Gram ----------------
__device__ __forceinline__ void mma_tf32(float* c, const uint32_t* a, uint32_t b0, uint32_t b1) {
    asm volatile(
        "mma.sync.aligned.m16n8k8.row.col.f32.tf32.tf32.f32 "
        "{%0,%1,%2,%3}, {%4,%5,%6,%7}, {%8,%9}, {%0,%1,%2,%3};"
        : "+f"(c[0]), "+f"(c[1]), "+f"(c[2]), "+f"(c[3])
        : "r"(a[0]), "r"(a[1]), "r"(a[2]), "r"(a[3]), "r"(b0), "r"(b1));
}

__global__ __launch_bounds__(256, 2) void k_gram(const float* __restrict__ X, int mode) {
    __shared__ float As[128 * AST];
    __shared__ float Bs[NP * AST];
    int tx = threadIdx.x, wid = tx >> 5, lane = tx & 31;
    int g = lane >> 2, tig = lane & 3;
    int wm = wid & 3, wn = wid >> 2;
    int j0 = blockIdx.x * 128;
    int sbase = blockIdx.y * (MS / KSPLIT);
    int nbase = wn * 9;
    int ntiles = wn ? 8 : 9;

    float c[2][9][4];
    #pragma unroll
    for (int tm = 0; tm < 2; tm++)
        #pragma unroll
        for (int nt = 0; nt < 9; nt++)
            #pragma unroll
            for (int q = 0; q < 4; q++) c[tm][nt][q] = 0.f;

    for (int ch = 0; ch < (MS / KSPLIT) / 32; ch++) {
        int s0 = sbase + ch * 32;
        __syncthreads();
        if (mode == 0) {
            #pragma unroll
            for (int k = 0; k < 16; k++) {
                int e = tx + k * 256; int jj = e & 127, s = e >> 7;
                float x = X[(size_t)(s0 + s) * MS + j0 + jj];
                As[jj * AST + s] = (x != 0.f) ? 1.f : 0.f;
            }
        } else {
            #pragma unroll
            for (int k = 0; k < 16; k++) {
                int e = tx + k * 256; int ii = e >> 5, s = e & 31;
                float x = X[(size_t)(j0 + ii) * MS + s0 + s];
                As[ii * AST + s] = (x != 0.f) ? 1.f : 0.f;
            }
        }
        #pragma unroll
        for (int k = 0; k < 17; k++) {
            int e = tx + k * 256; int p = e >> 5, s = e & 31;
            Bs[p * AST + s] = g_Pt[(size_t)p * MS + s0 + s];
        }
        __syncthreads();

        #pragma unroll
        for (int t = 0; t < 4; t++) {
            int kc = t * 8;
            uint32_t a[2][4];
            #pragma unroll
            for (int tm = 0; tm < 2; tm++) {
                int r0 = wm * 32 + tm * 16;
                a[tm][0] = __float_as_uint(As[(r0 + g) * AST + kc + tig]);
                a[tm][1] = __float_as_uint(As[(r0 + g + 8) * AST + kc + tig]);
                a[tm][2] = __float_as_uint(As[(r0 + g) * AST + kc + tig + 4]);
                a[tm][3] = __float_as_uint(As[(r0 + g + 8) * AST + kc + tig + 4]);
            }
            #pragma unroll
            for (int nt = 0; nt < 9; nt++) {
                if (nt < ntiles) {
                    int n0 = (nbase + nt) * 8;
                    uint32_t b0 = __float_as_uint(Bs[(n0 + g) * AST + kc + tig]);
                    uint32_t b1 = __float_as_uint(Bs[(n0 + g) * AST + kc + tig + 4]);
                    mma_tf32(c[0][nt], a[0], b0, b1);
                    mma_tf32(c[1][nt], a[1], b0, b1);
                }
            }
        }
    }

    size_t base = (size_t)blockIdx.y * NP * MS;
    #pragma unroll
    for (int tm = 0; tm < 2; tm++) {
        int row = j0 + wm * 32 + tm * 16 + g;
        #pragma unroll
        for (int nt = 0; nt < 9; nt++) {
            if (nt < ntiles) {
                int p0 = (nbase + nt) * 8 + 2 * tig;
                g_Apart[base + (size_t)p0 * MS + row]           = c[tm][nt][0];
                g_Apart[base + (size_t)(p0 + 1) * MS + row]     = c[tm][nt][1];
                g_Apart[base + (size_t)p0 * MS + row + 8]       = c[tm][nt][2];
                g_Apart[base + (size_t)(p0 + 1) * MS + row + 8] = c[tm][nt][3];
            }
        }
    }
}

// ---------------- reduce partials + ridge, invert 16x16; also init sigma ----------------
__global__ void k_inv(const float* __restrict__ sigma) {
    __shared__ float Mm[16][33];
    int t = threadIdx.x;
    int r = t >> 4, cc = t & 15;
    int i = blockIdx.x;
    if (t == 0) g_sig[i] = sigma[0];

    int rr = max(r, cc), cs = min(r, cc);
    int p = rr * (rr + 1) / 2 + cs;
    float sum = 0.f;
    #pragma unroll
    for (int sp = 0; sp < KSPLIT; sp++)
        sum += g_Apart[(size_t)sp * NP * MS + (size_t)p * MS + i];
    if (r == cc) sum += EPSR;
    Mm[r][cc] = sum;
    Mm[r][cc + 16] = (r == cc) ? 1.f : 0.f;
    __syncthreads();

    for (int k = 0; k < 16; k++) {
        float piv = Mm[k][k];
        __syncthreads();
        if (r == k) {
            float pivinv = 1.f / piv;
            Mm[k][cc] *= pivinv;
            Mm[k][cc + 16] *= pivinv;
        }
        __syncthreads();
        float f = Mm[r][k];
        float mk1 = Mm[k][cc];
        float mk2 = Mm[k][cc + 16];
        __syncthreads();
        if (r != k) {
            Mm[r][cc] -= f * mk1;
            Mm[r][cc + 16] -= f * mk2;
        }
        __syncthreads();
    }
    g_Ainv[(size_t)i * 256 + r * 16 + cc] = Mm[r][cc + 16];
}

// ================= col-mode (1 column per thread, 256 CTAs) =================
__global__ __launch_bounds__(256) void k_res_col(const float* __restrict__ X) {
    __shared__ float sF[TS * RD];
    int tx = threadIdx.x;
    int j = blockIdx.x * 256 + tx;
    int s0 = blockIdx.y * TS;
    #pragma unroll
    for (int k = 0; k < 16; k++)
        sF[tx + k * 256] = g_U[s0 * RD + tx + k * 256];
    float b[RD];
    #pragma unroll
    for (int q = 0; q < 4; q++) {
        float4 v = ((const float4*)(g_Vt + j * RD))[q];
        b[q*4+0]=v.x; b[q*4+1]=v.y; b[q*4+2]=v.z; b[q*4+3]=v.w;
    }
    float cl = g_coef[0];
    float inv_sig = 1.f / g_sig[j];
    __syncthreads();

    float acc = 0.f;
    for (int s = 0; s < TS; s++) {
        float d = X[(size_t)(s0 + s) * MS + j];
        float dot = 0.f;
        #pragma unroll
        for (int r = 0; r < RD; r++) dot += sF[s * RD + r] * b[r];
        float rv = (d != 0.f) ? (d - dot) : 0.f;
        float ps = fminf(fmaxf(rv * inv_sig, -cl), cl);
        acc += ps * ps;
    }
    g_ssqpart[blockIdx.y * MS + j] = acc;
}

// t pass with fused sigma computation
__global__ __launch_bounds__(256) void k_t_col(const float* __restrict__ X) {
    __shared__ float sF[TS * RD];
    int tx = threadIdx.x;
    int j = blockIdx.x * 256 + tx;
    int s0 = blockIdx.y * TS;
    #pragma unroll
    for (int k = 0; k < 16; k++)
        sF[tx + k * 256] = g_U[s0 * RD + tx + k * 256];
    float b[RD];
    #pragma unroll
    for (int q = 0; q < 4; q++) {
        float4 v = ((const float4*)(g_Vt + j * RD))[q];
        b[q*4+0]=v.x; b[q*4+1]=v.y; b[q*4+2]=v.z; b[q*4+3]=v.w;
    }
    // sigma from ssq partials
    float ss = 0.f;
    #pragma unroll
    for (int sp = 0; sp < SPL; sp++) ss += g_ssqpart[sp * MS + j];
    float cl = g_coef[0], ll = g_coef[1], alpha = g_coef[3];
    float sg = ll * sqrtf(ss) / sqrtf(2.f * g_cntc[j] * alpha);
    if (blockIdx.y == 0) g_sig[j] = sg;
    float thr = cl * sg;
    __syncthreads();

    float acc[RD];
    #pragma unroll
    for (int r = 0; r < RD; r++) acc[r] = 0.f;
    for (int s = 0; s < TS; s++) {
        float d = X[(size_t)(s0 + s) * MS + j];
        float dot = 0.f;
        #pragma unroll
        for (int r = 0; r < RD; r++) dot += sF[s * RD + r] * b[r];
        float rv = (d != 0.f) ? (d - dot) : 0.f;
        float pc = fminf(fmaxf(rv, -thr), thr);
        #pragma unroll
        for (int r = 0; r < RD; r++) acc[r] += sF[s * RD + r] * pc;
    }
    float* o = g_tpart + ((size_t)blockIdx.y * MS + j) * RD;
    #pragma unroll
    for (int q = 0; q < 4; q++)
        ((float4*)o)[q] = make_float4(acc[q*4], acc[q*4+1], acc[q*4+2], acc[q*4+3]);
}

// fused reduce-t + update (col): Vt[i] += mu * Ainv[i] @ t[i]
__global__ void k_updcol() {
    __shared__ float ts[256];
    int tx = threadIdx.x;
    int tid = blockIdx.x * 256 + tx;
    int i = tid >> 4, r = tid & 15;
    float s = 0.f;
    #pragma unroll
    for (int sp = 0; sp < SPL; sp++)
        s += g_tpart[((size_t)sp * MS + i) * RD + r];
    ts[tx] = s;
    __syncthreads();
    const float* Ai = g_Ainv + (size_t)i * 256 + r * 16;
    const float* ti = ts + (tx & ~15);
    float delta = 0.f;
    #pragma unroll
    for (int q = 0; q < RD; q++) delta += Ai[q] * ti[q];
    g_Vt[tid] += g_coef[2] * delta;
}

// ================= row-mode (warp per row) =================
__global__ __launch_bounds__(256) void k_res_row(const float* __restrict__ X) {
    __shared__ float sV[RD * 513];
    int tx = threadIdx.x, wid = tx >> 5, lane = tx & 31;
    int i = blockIdx.x * 8 + wid;
    float b[RD];
    #pragma unroll
    for (int r = 0; r < RD; r++) b[r] = g_U[i * RD + r];
    float cl = g_coef[0];
    float inv_sig = 1.f / g_sig[i];

    float acc = 0.f;
    for (int t = 0; t < 8; t++) {
        __syncthreads();
        #pragma unroll
        for (int k = 0; k < 32; k++) {
            int idx = tx + k * 256;
            int s = idx >> 4, r = idx & 15;
            sV[r * 513 + s] = g_Vt[t * 8192 + idx];
        }
        __syncthreads();
        #pragma unroll 2
        for (int k = 0; k < 16; k++) {
            int s = lane + k * 32;
            float d = X[(size_t)i * MS + t * 512 + s];
            float dot = 0.f;
            #pragma unroll
            for (int r = 0; r < RD; r++) dot += sV[r * 513 + s] * b[r];
            float rv = (d != 0.f) ? (d - dot) : 0.f;
            float ps = fminf(fmaxf(rv * inv_sig, -cl), cl);
            acc += ps * ps;
        }
    }
    #pragma unroll
    for (int off = 16; off; off >>= 1) acc += __shfl_xor_sync(~0u, acc, off);
    if (lane == 0) g_ssq[i] = acc;
}

// t pass with fused sigma + fused B update (row)
__global__ __launch_bounds__(256) void k_t_row(const float* __restrict__ X) {
    __shared__ float sV[RD * 513];
    int tx = threadIdx.x, wid = tx >> 5, lane = tx & 31;
    int i = blockIdx.x * 8 + wid;
    float b[RD];
    #pragma unroll
    for (int r = 0; r < RD; r++) b[r] = g_U[i * RD + r];
    float cl = g_coef[0], ll = g_coef[1], alpha = g_coef[3];
    float sg = ll * sqrtf(g_ssq[i]) / sqrtf(2.f * g_cntr[i] * alpha);
    float thr = cl * sg;

    float acc[RD];
    #pragma unroll
    for (int r = 0; r < RD; r++) acc[r] = 0.f;
    for (int t = 0; t < 8; t++) {
        __syncthreads();
        #pragma unroll
        for (int k = 0; k < 32; k++) {
            int idx = tx + k * 256;
            int s = idx >> 4, r = idx & 15;
            sV[r * 513 + s] = g_Vt[t * 8192 + idx];
        }
        __syncthreads();
        #pragma unroll 2
        for (int k = 0; k < 16; k++) {
            int s = lane + k * 32;
            float d = X[(size_t)i * MS + t * 512 + s];
            float dot = 0.f;
            #pragma unroll
            for (int r = 0; r < RD; r++) dot += sV[r * 513 + s] * b[r];
            float rv = (d != 0.f) ? (d - dot) : 0.f;
            float pc = fminf(fmaxf(rv, -thr), thr);
            #pragma unroll
            for (int r = 0; r < RD; r++) acc[r] += sV[r * 513 + s] * pc;
        }
    }
    // butterfly: after this every lane holds the full t[16]
    #pragma unroll
    for (int r = 0; r < RD; r++) {
        #pragma unroll
        for (int off = 16; off; off >>= 1)
            acc[r] += __shfl_xor_sync(~0u, acc[r], off);
    }
    if (lane == 0) g_sig[i] = sg;
    // fused update: lanes 0..15 apply delta = Ainv[i] row(lane) . t
    if (lane < 16) {
        const float4* Ai = (const float4*)(g_Ainv + (size_t)i * 256 + lane * 16);
        float delta = 0.f;
        #pragma unroll
        for (int q = 0; q < 4; q++) {
            float4 a4 = Ai[q];
            delta += a4.x * acc[q*4] + a4.y * acc[q*4+1] + a4.z * acc[q*4+2] + a4.w * acc[q*4+3];
        }
        g_U[i * RD + lane] += g_coef[2] * delta;
    }
}

// ---------------- final out = U @ V ----------------
__global__ void k_out(float* __restrict__ out) {
    __shared__ float sU[64 * RD];
    int tx = threadIdx.x;
    int n = blockIdx.x * 256 + tx;
    int m0 = blockIdx.y * 64;
    #pragma unroll
    for (int k = 0; k < 4; k++)
        sU[tx + k * 256] = g_U[m0 * RD + tx + k * 256];
    float v[RD];
    #pragma unroll
    for (int r = 0; r < RD; r++) v[r] = g_Vt[n * RD + r];
    __syncthreads();
    for (int j = 0; j < 64; j++) {
        float dot = 0.f;
        #pragma unroll
        for (int r = 0; r < RD; r++) dot += sU[j * RD + r] * v[r];
        out[(size_t)(m0 + j) * MS + n] = dot;
    }
}

// ---------------- orchestration ----------------
extern "C" void kernel_launch(void* const* d_in, const int* in_sizes, int n_in,
                              void* d_out, int out_size) {
    const float* U_in  = (const float*)d_in[0];
    const float* V_in  = (const float*)d_in[1];
    const float* X     = (const float*)d_in[2];
    const float* c_in  = (const float*)d_in[3];
    const float* l_in  = (const float*)d_in[4];
    const float* m_in  = (const float*)d_in[5];
    const float* sg_in = (const float*)d_in[6];
    float* out = (float*)d_out;

    dim3 b256(256);
    dim3 gcol(16, SPL);         // 256 CTAs for col-mode
    dim3 ggram(32, KSPLIT);

    k_setup<<<256, 256>>>(U_in, V_in);
    k_cnt_col<<<gcol, b256>>>(X);
    k_cnt_fin<<<16, 256>>>();
    k_cnt_row<<<512, 256>>>(X);

    for (int layer = 0; layer < 3; layer++) {
        // ---- V step (col-mode) ----
        k_P<<<16, 256>>>(0, 1, c_in, l_in, m_in, layer);
        k_gram<<<ggram, b256>>>(X, 0);
        k_inv<<<4096, 256>>>(sg_in);
        for (int it = 0; it < 2; it++) {
            k_res_col<<<gcol, b256>>>(X);
            k_t_col<<<gcol, b256>>>(X);
            k_updcol<<<256, 256>>>();
        }

        // ---- U step (row-mode) ----
        k_P<<<16, 256>>>(1, 0, c_in, l_in, m_in, layer);
        k_gram<<<ggram, b256>>>(X, 1);
        k_inv<<<4096, 256>>>(sg_in);
        for (int it = 0; it < 2; it++) {
            k_res_row<<<512, 256>>>(X);
            k_t_row<<<512, 256>>>(X);
        }
    }

    k_out<<<dim3(16, 64), 256>>>(out);
}

// round 7
// speedup vs baseline: 1.4555x; 1.0683x over previous
#include <cuda_runtime.h>
#include <math.h>
#include <stdint.h>

#define MS 4096            // square: M == N == 4096
#define RD 16
#define NP 136             // 16*17/2 symmetric pairs
#define KSPLIT 4           // split-K for gram
#define EPSR 1e-5f
#define AST 36             // smem row stride (floats) for mma tiles
#define FST 20             // smem row stride for hubreg F staging (conflict-free float4)

// ---------------- scratch (~80 MB of device globals) ----------------
__device__ float g_Xt[(size_t)MS * MS];              // 64 MB  X transposed
__device__ float g_Apart[(size_t)KSPLIT * NP * MS];  // 8.9 MB gram partials
__device__ float g_Ainv[(size_t)MS * RD * RD];       // 4.0 MB
__device__ float g_Pt[(size_t)NP * MS];              // 2.2 MB Pt [p][s] (tf32 values)
__device__ float g_U[MS * RD];
__device__ float g_Vt[MS * RD];                      // V transposed: [n][r]
__device__ float g_cntc[MS];
__device__ float g_cntr[MS];
__device__ float g_coef[4];                          // c, lamda, mu, alpha

// ---------------- setup: copy U, transpose V ----------------
__global__ void k_setup(const float* __restrict__ U, const float* __restrict__ V) {
    int tid = blockIdx.x * 256 + threadIdx.x;
    g_U[tid] = U[tid];
    int n = tid >> 4, r = tid & 15;
    g_Vt[tid] = V[r * MS + n];
}

// ---------------- X transpose (32x32 tiles) ----------------
__global__ void k_transpose(const float* __restrict__ X) {
    __shared__ float tile[32][33];
    int x = blockIdx.x * 32 + threadIdx.x;
    int y0 = blockIdx.y * 32;
    #pragma unroll
    for (int j = threadIdx.y; j < 32; j += 8)
        tile[j][threadIdx.x] = X[(size_t)(y0 + j) * MS + x];
    __syncthreads();
    int xo = blockIdx.y * 32 + threadIdx.x;
    int yo0 = blockIdx.x * 32;
    #pragma unroll
    for (int j = threadIdx.y; j < 32; j += 8)
        g_Xt[(size_t)(yo0 + j) * MS + xo] = tile[threadIdx.x][j];
}

// ---------------- row-style counts (warp per row of D) ----------------
__global__ void k_cnt(const float* __restrict__ D, float* __restrict__ cnt) {
    int wid = threadIdx.x >> 5, lane = threadIdx.x & 31;
    int i = blockIdx.x * 8 + wid;
    float c = 0.f;
    for (int s = lane; s < MS; s += 32)
        c += (D[(size_t)i * MS + s] != 0.f) ? 1.f : 0.f;
    #pragma unroll
    for (int off = 16; off; off >>= 1) c += __shfl_xor_sync(~0u, c, off);
    if (lane == 0) cnt[i] = c;
}

// ---------------- P build (+ per-layer coefficients when do_coef) ----------------
__global__ void k_P(int mode, int do_coef, const float* __restrict__ cc,
                    const float* __restrict__ lam, const float* __restrict__ mu, int layer) {
    if (do_coef && blockIdx.x == 0 && threadIdx.x == 0) {
        double cl = (double)cc[layer];
        double chi1 = erf(sqrt(cl));
        double y = 0.5 * cl * cl;
        double chi3 = erf(sqrt(y)) - 2.0 * sqrt(y) * exp(-y) / sqrt(3.14159265358979323846);
        double alpha = cl * (1.0 - chi1) + 0.5 * chi3;
        g_coef[0] = (float)cl;
        g_coef[1] = lam[layer];
        g_coef[2] = mu[layer];
        g_coef[3] = (float)alpha;
    }
    int s = blockIdx.x * 256 + threadIdx.x;
    const float* F = mode ? g_Vt : g_U;
    float u[RD];
    const float4* f4 = (const float4*)(F + s * RD);
    #pragma unroll
    for (int q = 0; q < 4; q++) {
        float4 v = f4[q];
        u[q * 4 + 0] = v.x; u[q * 4 + 1] = v.y; u[q * 4 + 2] = v.z; u[q * 4 + 3] = v.w;
    }
    #pragma unroll
    for (int r = 0; r < RD; r++) {
        #pragma unroll
        for (int c2 = 0; c2 <= r; c2++) {
            float v = u[r] * u[c2];
            uint32_t t;
            asm("cvt.rna.tf32.f32 %0, %1;" : "=r"(t) : "f"(v));
            g_Pt[(size_t)(r * (r + 1) / 2 + c2) * MS + s] = __uint_as_float(t);
        }
    }
}

// ---------------- tf32 mma.sync Gram (row-mode on D) ----------------
__device__ __forceinline__ void mma_tf32(float* c, const uint32_t* a, uint32_t b0, uint32_t b1) {
    asm volatile(
        "mma.sync.aligned.m16n8k8.row.col.f32.tf32.tf32.f32 "
        "{%0,%1,%2,%3}, {%4,%5,%6,%7}, {%8,%9}, {%0,%1,%2,%3};"
        : "+f"(c[0]), "+f"(c[1]), "+f"(c[2]), "+f"(c[3])
        : "r"(a[0]), "r"(a[1]), "r"(a[2]), "r"(a[3]), "r"(b0), "r"(b1));
}

__global__ __launch_bounds__(256, 2) void k_gram(const float* __restrict__ D) {
    __shared__ float As[128 * AST];
    __shared__ float Bs[NP * AST];
    int tx = threadIdx.x, wid = tx >> 5, lane = tx & 31;
    int g = lane >> 2, tig = lane & 3;
    int wm = wid & 3, wn = wid >> 2;
    int j0 = blockIdx.x * 128;
    int sbase = blockIdx.y * (MS / KSPLIT);
    int nbase = wn * 9;
    int ntiles = wn ? 8 : 9;

    float c[2][9][4];
    #pragma unroll
    for (int tm = 0; tm < 2; tm++)
        #pragma unroll
        for (int nt = 0; nt < 9; nt++)
            #pragma unroll
            for (int q = 0; q < 4; q++) c[tm][nt][q] = 0.f;

    for (int ch = 0; ch < (MS / KSPLIT) / 32; ch++) {
        int s0 = sbase + ch * 32;
        __syncthreads();
        #pragma unroll
        for (int k = 0; k < 16; k++) {
            int e = tx + k * 256; int ii = e >> 5, s = e & 31;
            float x = D[(size_t)(j0 + ii) * MS + s0 + s];
            As[ii * AST + s] = (x != 0.f) ? 1.f : 0.f;
        }
        #pragma unroll
        for (int k = 0; k < 17; k++) {
            int e = tx + k * 256; int p = e >> 5, s = e & 31;
            Bs[p * AST + s] = g_Pt[(size_t)p * MS + s0 + s];
        }
        __syncthreads();

        #pragma unroll
        for (int t = 0; t < 4; t++) {
            int kc = t * 8;
            uint32_t a[2][4];
            #pragma unroll
            for (int tm = 0; tm < 2; tm++) {
                int r0 = wm * 32 + tm * 16;
                a[tm][0] = __float_as_uint(As[(r0 + g) * AST + kc + tig]);
                a[tm][1] = __float_as_uint(As[(r0 + g + 8) * AST + kc + tig]);
                a[tm][2] = __float_as_uint(As[(r0 + g) * AST + kc + tig + 4]);
                a[tm][3] = __float_as_uint(As[(r0 + g + 8) * AST + kc + tig + 4]);
            }
            #pragma unroll
            for (int nt = 0; nt < 9; nt++) {
                if (nt < ntiles) {
                    int n0 = (nbase + nt) * 8;
                    uint32_t b0 = __float_as_uint(Bs[(n0 + g) * AST + kc + tig]);
                    uint32_t b1 = __float_as_uint(Bs[(n0 + g) * AST + kc + tig + 4]);
                    mma_tf32(c[0][nt], a[0], b0, b1);
                    mma_tf32(c[1][nt], a[1], b0, b1);
                }
            }
        }
    }

    size_t base = (size_t)blockIdx.y * NP * MS;
    #pragma unroll
    for (int tm = 0; tm < 2; tm++) {
        int row = j0 + wm * 32 + tm * 16 + g;
        #pragma unroll
        for (int nt = 0; nt < 9; nt++) {
            if (nt < ntiles) {
                int p0 = (nbase + nt) * 8 + 2 * tig;
                g_Apart[base + (size_t)p0 * MS + row]           = c[tm][nt][0];
                g_Apart[base + (size_t)(p0 + 1) * MS + row]     = c[tm][nt][1];
                g_Apart[base + (size_t)p0 * MS + row + 8]       = c[tm][nt][2];
                g_Apart[base + (size_t)(p0 + 1) * MS + row + 8] = c[tm][nt][3];
            }
        }
    }
}

// ---------------- reduce partials + ridge, invert 16x16 ----------------
__global__ void k_inv() {
    __shared__ float Mm[16][33];
    int t = threadIdx.x;
    int r = t >> 4, cc = t & 15;
    int i = blockIdx.x;

    int rr = max(r, cc), cs = min(r, cc);
    int p = rr * (rr + 1) / 2 + cs;
    float sum = 0.f;
    #pragma unroll
    for (int sp = 0; sp < KSPLIT; sp++)
        sum += g_Apart[(size_t)sp * NP * MS + (size_t)p * MS + i];
    if (r == cc) sum += EPSR;
    Mm[r][cc] = sum;
    Mm[r][cc + 16] = (r == cc) ? 1.f : 0.f;
    __syncthreads();

    for (int k = 0; k < 16; k++) {
        float piv = Mm[k][k];
        __syncthreads();
        if (r == k) {
            float pivinv = 1.f / piv;
            Mm[k][cc] *= pivinv;
            Mm[k][cc + 16] *= pivinv;
        }
        __syncthreads();
        float f = Mm[r][k];
        float mk1 = Mm[k][cc];
        float mk2 = Mm[k][cc + 16];
        __syncthreads();
        if (r != k) {
            Mm[r][cc] -= f * mk1;
            Mm[r][cc + 16] -= f * mk2;
        }
        __syncthreads();
    }
    g_Ainv[(size_t)i * 256 + r * 16 + cc] = Mm[r][cc + 16];
}

// ---------------- fully fused hubreg: warp per item, both iterations ----------------
// mode 0 (V step): D=g_Xt, F=g_U,  B=g_Vt, cnt=g_cntc
// mode 1 (U step): D=g_X(input), F=g_Vt, B=g_U, cnt=g_cntr
__global__ __launch_bounds__(256) void k_hubreg(const float* __restrict__ D, int mode,
                                                const float* __restrict__ sg_in) {
    __shared__ float sF[512 * FST];          // 40 KB staging of F chunk
    int tx = threadIdx.x, wid = tx >> 5, lane = tx & 31;
    int i = blockIdx.x * 8 + wid;
    const float* F = mode ? g_Vt : g_U;
    float* B = mode ? g_U : g_Vt;
    float cnt = (mode ? g_cntr : g_cntc)[i];
    float cl = g_coef[0], ll = g_coef[1], ml = g_coef[2], alpha = g_coef[3];
    float denom = rsqrtf(2.f * cnt * alpha);

    float b[RD];
    #pragma unroll
    for (int q = 0; q < 4; q++) {
        float4 v = ((const float4*)(B + i * RD))[q];
        b[q*4+0]=v.x; b[q*4+1]=v.y; b[q*4+2]=v.z; b[q*4+3]=v.w;
    }
    float sg = sg_in[0];

    #pragma unroll 1
    for (int iter = 0; iter < 2; iter++) {
        // ---- sweep A: ssq of clipped normalized residual ----
        float inv_sg = 1.f / sg;
        float ssq = 0.f;
        #pragma unroll 1
        for (int t = 0; t < 8; t++) {
            __syncthreads();
            #pragma unroll
            for (int k = 0; k < 32; k++) {
                int e = tx + k * 256;
                sF[(e >> 4) * FST + (e & 15)] = F[t * 8192 + e];
            }
            __syncthreads();
            #pragma unroll 4
            for (int k = 0; k < 16; k++) {
                int s = lane + k * 32;
                float d = D[(size_t)i * MS + t * 512 + s];
                const float4* f4 = (const float4*)(sF + s * FST);
                float dot = 0.f;
                #pragma unroll
                for (int q = 0; q < 4; q++) {
                    float4 f = f4[q];
                    dot += f.x*b[q*4] + f.y*b[q*4+1] + f.z*b[q*4+2] + f.w*b[q*4+3];
                }
                float rv = (d != 0.f) ? (d - dot) : 0.f;
                float ps = fminf(fmaxf(rv * inv_sg, -cl), cl);
                ssq += ps * ps;
            }
        }
        #pragma unroll
        for (int off = 16; off; off >>= 1) ssq += __shfl_xor_sync(~0u, ssq, off);
        sg = ll * sqrtf(ssq) * denom;
        float thr = cl * sg;

        // ---- sweep B: t accumulation ----
        float acc[RD];
        #pragma unroll
        for (int r = 0; r < RD; r++) acc[r] = 0.f;
        #pragma unroll 1
        for (int t = 0; t < 8; t++) {
            __syncthreads();
            #pragma unroll
            for (int k = 0; k < 32; k++) {
                int e = tx + k * 256;
                sF[(e >> 4) * FST + (e & 15)] = F[t * 8192 + e];
            }
            __syncthreads();
            #pragma unroll 4
            for (int k = 0; k < 16; k++) {
                int s = lane + k * 32;
                float d = D[(size_t)i * MS + t * 512 + s];
                const float4* f4 = (const float4*)(sF + s * FST);
                float4 f0 = f4[0], f1 = f4[1], f2 = f4[2], f3 = f4[3];
                float dot = f0.x*b[0] + f0.y*b[1] + f0.z*b[2] + f0.w*b[3]
                          + f1.x*b[4] + f1.y*b[5] + f1.z*b[6] + f1.w*b[7]
                          + f2.x*b[8] + f2.y*b[9] + f2.z*b[10] + f2.w*b[11]
                          + f3.x*b[12] + f3.y*b[13] + f3.z*b[14] + f3.w*b[15];
                float rv = (d != 0.f) ? (d - dot) : 0.f;
                float pc = fminf(fmaxf(rv, -thr), thr);
                acc[0]+=f0.x*pc;  acc[1]+=f0.y*pc;  acc[2]+=f0.z*pc;  acc[3]+=f0.w*pc;
                acc[4]+=f1.x*pc;  acc[5]+=f1.y*pc;  acc[6]+=f1.z*pc;  acc[7]+=f1.w*pc;
                acc[8]+=f2.x*pc;  acc[9]+=f2.y*pc;  acc[10]+=f2.z*pc; acc[11]+=f2.w*pc;
                acc[12]+=f3.x*pc; acc[13]+=f3.y*pc; acc[14]+=f3.z*pc; acc[15]+=f3.w*pc;
            }
        }
        #pragma unroll
        for (int r = 0; r < RD; r++) {
            #pragma unroll
            for (int off = 16; off; off >>= 1)
                acc[r] += __shfl_xor_sync(~0u, acc[r], off);
        }
        // delta_r computed by lane r, broadcast so all lanes update b
        float delta = 0.f;
        if (lane < 16) {
            const float4* Ai = (const float4*)(g_Ainv + (size_t)i * 256 + lane * 16);
            #pragma unroll
            for (int q = 0; q < 4; q++) {
                float4 a4 = Ai[q];
                delta += a4.x*acc[q*4] + a4.y*acc[q*4+1] + a4.z*acc[q*4+2] + a4.w*acc[q*4+3];
            }
        }
        #pragma unroll
        for (int r = 0; r < RD; r++)
            b[r] += ml * __shfl_sync(~0u, delta, r);
    }

    if (lane < 16) B[i * RD + lane] = b[lane];
}

// ---------------- final out = U @ V ----------------
__global__ void k_out(float* __restrict__ out) {
    __shared__ float sU[64 * RD];
    int tx = threadIdx.x;
    int n = blockIdx.x * 256 + tx;
    int m0 = blockIdx.y * 64;
    #pragma unroll
    for (int k = 0; k < 4; k++)
        sU[tx + k * 256] = g_U[m0 * RD + tx + k * 256];
    float v[RD];
    #pragma unroll
    for (int r = 0; r < RD; r++) v[r] = g_Vt[n * RD + r];
    __syncthreads();
    for (int j = 0; j < 64; j++) {
        float dot = 0.f;
        #pragma unroll
        for (int r = 0; r < RD; r++) dot += sU[j * RD + r] * v[r];
        out[(size_t)(m0 + j) * MS + n] = dot;
    }
}

// ---------------- orchestration ----------------
extern "C" void kernel_launch(void* const* d_in, const int* in_sizes, int n_in,
                              void* d_out, int out_size) {
    const float* U_in  = (const float*)d_in[0];
    const float* V_in  = (const float*)d_in[1];
    const float* X     = (const float*)d_in[2];
    const float* c_in  = (const float*)d_in[3];
    const float* l_in  = (const float*)d_in[4];
    const float* m_in  = (const float*)d_in[5];
    const float* sg_in = (const float*)d_in[6];
    float* out = (float*)d_out;

    float* Xt;
    { void* p; cudaGetSymbolAddress(&p, g_Xt); Xt = (float*)p; }
    float* cntc; { void* p; cudaGetSymbolAddress(&p, g_cntc); cntc = (float*)p; }
    float* cntr; { void* p; cudaGetSymbolAddress(&p, g_cntr); cntr = (float*)p; }

    dim3 b256(256);
    dim3 ggram(32, KSPLIT);

    k_setup<<<256, 256>>>(U_in, V_in);
    k_transpose<<<dim3(128, 128), dim3(32, 8)>>>(X);
    k_cnt<<<512, 256>>>(X, cntr);
    k_cnt<<<512, 256>>>(Xt, cntc);

    for (int layer = 0; layer < 3; layer++) {
        // ---- V step: items = columns of X (rows of Xt), F = U, B = Vt ----
        k_P<<<16, 256>>>(0, 1, c_in, l_in, m_in, layer);
        k_gram<<<ggram, b256>>>(Xt);
        k_inv<<<4096, 256>>>();
        k_hubreg<<<512, 256>>>(Xt, 0, sg_in);

        // ---- U step: items = rows of X, F = Vt, B = U ----
        k_P<<<16, 256>>>(1, 0, c_in, l_in, m_in, layer);
        k_gram<<<ggram, b256>>>(X);
        k_inv<<<4096, 256>>>();
        k_hubreg<<<512, 256>>>(X, 1, sg_in);
    }

    k_out<<<dim3(16, 64), 256>>>(out);
}

// round 8
// speedup vs baseline: 1.6049x; 1.1026x over previous
#include <cuda_runtime.h>
#include <math.h>
#include <stdint.h>

#define MS 4096            // square: M == N == 4096
#define RD 16
#define NP 136             // 16*17/2 symmetric pairs
#define KSPLIT 8           // split-K for gram
#define EPSR 1e-5f
#define AST 36             // smem row stride (floats) for mma tiles
#define FST 20             // smem row stride for hubreg F staging

// gram smem layout (bytes)
#define GA0 0
#define GA1 18432
#define GB0 36864
#define GB1 56448
#define GSM 76032

// ---------------- scratch (~90 MB of device globals) ----------------
__device__ float g_Xt[(size_t)MS * MS];              // 64 MB  X transposed
__device__ float g_Apart[(size_t)KSPLIT * NP * MS];  // 17.8 MB gram partials
__device__ float g_Ainv[(size_t)MS * RD * RD];       // 4.0 MB
__device__ float g_Pt[(size_t)NP * MS];              // 2.2 MB Pt [p][s] (tf32 values)
__device__ float g_U[MS * RD];
__device__ float g_Vt[MS * RD];                      // V transposed: [n][r]
__device__ float g_cntc[MS];
__device__ float g_cntr[MS];
__device__ float g_coef[4];                          // c, lamda, mu, alpha

__device__ __forceinline__ uint32_t smem_u32(const void* p) {
    uint32_t a;
    asm("{ .reg .u64 t; cvta.to.shared.u64 t, %1; cvt.u32.u64 %0, t; }" : "=r"(a) : "l"(p));
    return a;
}
#define CPA16(dst, src) \
    asm volatile("cp.async.ca.shared.global [%0], [%1], 16;" :: "r"(dst), "l"(src))
#define CPA_COMMIT() asm volatile("cp.async.commit_group;" ::: "memory")
#define CPA_WAIT1()  asm volatile("cp.async.wait_group 1;" ::: "memory")
#define CPA_WAIT0()  asm volatile("cp.async.wait_group 0;" ::: "memory")

// ---------------- setup: copy U, transpose V ----------------
__global__ void k_setup(const float* __restrict__ U, const float* __restrict__ V) {
    int tid = blockIdx.x * 256 + threadIdx.x;
    g_U[tid] = U[tid];
    int n = tid >> 4, r = tid & 15;
    g_Vt[tid] = V[r * MS + n];
}

// ---------------- X transpose (32x32 tiles) ----------------
__global__ void k_transpose(const float* __restrict__ X) {
    __shared__ float tile[32][33];
    int x = blockIdx.x * 32 + threadIdx.x;
    int y0 = blockIdx.y * 32;
    #pragma unroll
    for (int j = threadIdx.y; j < 32; j += 8)
        tile[j][threadIdx.x] = X[(size_t)(y0 + j) * MS + x];
    __syncthreads();
    int xo = blockIdx.y * 32 + threadIdx.x;
    int yo0 = blockIdx.x * 32;
    #pragma unroll
    for (int j = threadIdx.y; j < 32; j += 8)
        g_Xt[(size_t)(yo0 + j) * MS + xo] = tile[threadIdx.x][j];
}

// ---------------- row-style counts (warp per row of D) ----------------
__global__ void k_cnt(const float* __restrict__ D, float* __restrict__ cnt) {
    int wid = threadIdx.x >> 5, lane = threadIdx.x & 31;
    int i = blockIdx.x * 8 + wid;
    float c = 0.f;
    for (int s = lane; s < MS; s += 32)
        c += (D[(size_t)i * MS + s] != 0.f) ? 1.f : 0.f;
    #pragma unroll
    for (int off = 16; off; off >>= 1) c += __shfl_xor_sync(~0u, c, off);
    if (lane == 0) cnt[i] = c;
}

// ---------------- P build, p-split over blockIdx.y (+ coefficients) ----------------
__global__ void k_P(int mode, int do_coef, const float* __restrict__ cc,
                    const float* __restrict__ lam, const float* __restrict__ mu, int layer) {
    if (do_coef && blockIdx.x == 0 && blockIdx.y == 0 && threadIdx.x == 0) {
        double cl = (double)cc[layer];
        double chi1 = erf(sqrt(cl));
        double y = 0.5 * cl * cl;
        double chi3 = erf(sqrt(y)) - 2.0 * sqrt(y) * exp(-y) / sqrt(3.14159265358979323846);
        double alpha = cl * (1.0 - chi1) + 0.5 * chi3;
        g_coef[0] = (float)cl;
        g_coef[1] = lam[layer];
        g_coef[2] = mu[layer];
        g_coef[3] = (float)alpha;
    }
    int s = blockIdx.x * 256 + threadIdx.x;
    int plo = blockIdx.y * 34, phi = plo + 34;
    const float* F = mode ? g_Vt : g_U;
    float u[RD];
    const float4* f4 = (const float4*)(F + s * RD);
    #pragma unroll
    for (int q = 0; q < 4; q++) {
        float4 v = f4[q];
        u[q * 4 + 0] = v.x; u[q * 4 + 1] = v.y; u[q * 4 + 2] = v.z; u[q * 4 + 3] = v.w;
    }
    #pragma unroll
    for (int r = 0; r < RD; r++) {
        #pragma unroll
        for (int c2 = 0; c2 <= r; c2++) {
            int pidx = r * (r + 1) / 2 + c2;
            if (pidx >= plo && pidx < phi) {
                float v = u[r] * u[c2];
                uint32_t t;
                asm("cvt.rna.tf32.f32 %0, %1;" : "=r"(t) : "f"(v));
                g_Pt[(size_t)pidx * MS + s] = __uint_as_float(t);
            }
        }
    }
}

// ---------------- tf32 mma.sync Gram with cp.async double buffering ----------------
__device__ __forceinline__ void mma_tf32(float* c, const uint32_t* a, uint32_t b0, uint32_t b1) {
    asm volatile(
        "mma.sync.aligned.m16n8k8.row.col.f32.tf32.tf32.f32 "
        "{%0,%1,%2,%3}, {%4,%5,%6,%7}, {%8,%9}, {%0,%1,%2,%3};"
        : "+f"(c[0]), "+f"(c[1]), "+f"(c[2]), "+f"(c[3])
        : "r"(a[0]), "r"(a[1]), "r"(a[2]), "r"(a[3]), "r"(b0), "r"(b1));
}

__global__ __launch_bounds__(256, 2) void k_gram(const float* __restrict__ D) {
    extern __shared__ char sm[];
    uint32_t sb = smem_u32(sm);
    int tx = threadIdx.x, wid = tx >> 5, lane = tx & 31;
    int g = lane >> 2, tig = lane & 3;
    int wm = wid & 3, wn = wid >> 2;
    int j0 = blockIdx.x * 128;
    int sbase = blockIdx.y * (MS / KSPLIT);
    int nbase = wn * 9;
    int ntiles = wn ? 8 : 9;
    const int NCH = (MS / KSPLIT) / 32;   // 16 chunks

    // issue chunk ch into buffer b
    auto issue = [&](int ch, int b) {
        int s0 = sbase + ch * 32;
        uint32_t ab = sb + (b ? GA1 : GA0);
        uint32_t bb = sb + (b ? GB1 : GB0);
        int rA = tx >> 3, s4 = (tx & 7) * 4;
        #pragma unroll
        for (int k = 0; k < 4; k++) {
            int row = rA + k * 32;
            CPA16(ab + row * (AST * 4) + s4 * 4,
                  D + (size_t)(j0 + row) * MS + s0 + s4);
        }
        #pragma unroll
        for (int k = 0; k < 5; k++) {
            int e = tx + k * 256;
            int row = e >> 3, sb4 = (e & 7) * 4;
            if (row < NP)
                CPA16(bb + row * (AST * 4) + sb4 * 4,
                      g_Pt + (size_t)row * MS + s0 + sb4);
        }
        CPA_COMMIT();
    };

    float c[2][9][4];
    #pragma unroll
    for (int tm = 0; tm < 2; tm++)
        #pragma unroll
        for (int nt = 0; nt < 9; nt++)
            #pragma unroll
            for (int q = 0; q < 4; q++) c[tm][nt][q] = 0.f;

    issue(0, 0);
    for (int ch = 0; ch < NCH; ch++) {
        if (ch + 1 < NCH) { issue(ch + 1, (ch + 1) & 1); CPA_WAIT1(); }
        else              { CPA_WAIT0(); }
        __syncthreads();
        const float* As = (const float*)(sm + ((ch & 1) ? GA1 : GA0));
        const float* Bs = (const float*)(sm + ((ch & 1) ? GB1 : GB0));

        #pragma unroll
        for (int t = 0; t < 4; t++) {
            int kc = t * 8;
            uint32_t a[2][4];
            #pragma unroll
            for (int tm = 0; tm < 2; tm++) {
                int r0 = wm * 32 + tm * 16;
                float x0 = As[(r0 + g) * AST + kc + tig];
                float x1 = As[(r0 + g + 8) * AST + kc + tig];
                float x2 = As[(r0 + g) * AST + kc + tig + 4];
                float x3 = As[(r0 + g + 8) * AST + kc + tig + 4];
                a[tm][0] = (x0 != 0.f) ? 0x3F800000u : 0u;
                a[tm][1] = (x1 != 0.f) ? 0x3F800000u : 0u;
                a[tm][2] = (x2 != 0.f) ? 0x3F800000u : 0u;
                a[tm][3] = (x3 != 0.f) ? 0x3F800000u : 0u;
            }
            #pragma unroll
            for (int nt = 0; nt < 9; nt++) {
                if (nt < ntiles) {
                    int n0 = (nbase + nt) * 8;
                    uint32_t b0 = __float_as_uint(Bs[(n0 + g) * AST + kc + tig]);
                    uint32_t b1 = __float_as_uint(Bs[(n0 + g) * AST + kc + tig + 4]);
                    mma_tf32(c[0][nt], a[0], b0, b1);
                    mma_tf32(c[1][nt], a[1], b0, b1);
                }
            }
        }
        __syncthreads();
    }

    size_t base = (size_t)blockIdx.y * NP * MS;
    #pragma unroll
    for (int tm = 0; tm < 2; tm++) {
        int row = j0 + wm * 32 + tm * 16 + g;
        #pragma unroll
        for (int nt = 0; nt < 9; nt++) {
            if (nt < ntiles) {
                int p0 = (nbase + nt) * 8 + 2 * tig;
                g_Apart[base + (size_t)p0 * MS + row]           = c[tm][nt][0];
                g_Apart[base + (size_t)(p0 + 1) * MS + row]     = c[tm][nt][1];
                g_Apart[base + (size_t)p0 * MS + row + 8]       = c[tm][nt][2];
                g_Apart[base + (size_t)(p0 + 1) * MS + row + 8] = c[tm][nt][3];
            }
        }
    }
}

// ---------------- reduce partials + ridge, invert 16x16 ----------------
__global__ void k_inv() {
    __shared__ float Mm[16][33];
    int t = threadIdx.x;
    int r = t >> 4, cc = t & 15;
    int i = blockIdx.x;

    int rr = max(r, cc), cs = min(r, cc);
    int p = rr * (rr + 1) / 2 + cs;
    float sum = 0.f;
    #pragma unroll
    for (int sp = 0; sp < KSPLIT; sp++)
        sum += g_Apart[(size_t)sp * NP * MS + (size_t)p * MS + i];
    if (r == cc) sum += EPSR;
    Mm[r][cc] = sum;
    Mm[r][cc + 16] = (r == cc) ? 1.f : 0.f;
    __syncthreads();

    for (int k = 0; k < 16; k++) {
        float piv = Mm[k][k];
        __syncthreads();
        if (r == k) {
            float pivinv = 1.f / piv;
            Mm[k][cc] *= pivinv;
            Mm[k][cc + 16] *= pivinv;
        }
        __syncthreads();
        float f = Mm[r][k];
        float mk1 = Mm[k][cc];
        float mk2 = Mm[k][cc + 16];
        __syncthreads();
        if (r != k) {
            Mm[r][cc] -= f * mk1;
            Mm[r][cc + 16] -= f * mk2;
        }
        __syncthreads();
    }
    g_Ainv[(size_t)i * 256 + r * 16 + cc] = Mm[r][cc + 16];
}

// ---------------- fully fused hubreg: warp per item, both iterations ----------------
__global__ __launch_bounds__(256) void k_hubreg(const float* __restrict__ D, int mode,
                                                const float* __restrict__ sg_in) {
    __shared__ float sF[512 * FST];
    int tx = threadIdx.x, wid = tx >> 5, lane = tx & 31;
    int i = blockIdx.x * 8 + wid;
    const float* F = mode ? g_Vt : g_U;
    float* B = mode ? g_U : g_Vt;
    float cnt = (mode ? g_cntr : g_cntc)[i];
    float cl = g_coef[0], ll = g_coef[1], ml = g_coef[2], alpha = g_coef[3];
    float denom = rsqrtf(2.f * cnt * alpha);

    float b[RD];
    #pragma unroll
    for (int q = 0; q < 4; q++) {
        float4 v = ((const float4*)(B + i * RD))[q];
        b[q*4+0]=v.x; b[q*4+1]=v.y; b[q*4+2]=v.z; b[q*4+3]=v.w;
    }
    float sg = sg_in[0];

    #pragma unroll 1
    for (int iter = 0; iter < 2; iter++) {
        float inv_sg = 1.f / sg;
        float ssq = 0.f;
        #pragma unroll 1
        for (int t = 0; t < 8; t++) {
            __syncthreads();
            #pragma unroll
            for (int k = 0; k < 32; k++) {
                int e = tx + k * 256;
                sF[(e >> 4) * FST + (e & 15)] = F[t * 8192 + e];
            }
            __syncthreads();
            #pragma unroll 4
            for (int k = 0; k < 16; k++) {
                int s = lane + k * 32;
                float d = D[(size_t)i * MS + t * 512 + s];
                const float4* f4 = (const float4*)(sF + s * FST);
                float dot = 0.f;
                #pragma unroll
                for (int q = 0; q < 4; q++) {
                    float4 f = f4[q];
                    dot += f.x*b[q*4] + f.y*b[q*4+1] + f.z*b[q*4+2] + f.w*b[q*4+3];
                }
                float rv = (d != 0.f) ? (d - dot) : 0.f;
                float ps = fminf(fmaxf(rv * inv_sg, -cl), cl);
                ssq += ps * ps;
            }
        }
        #pragma unroll
        for (int off = 16; off; off >>= 1) ssq += __shfl_xor_sync(~0u, ssq, off);
        sg = ll * sqrtf(ssq) * denom;
        float thr = cl * sg;

        float acc[RD];
        #pragma unroll
        for (int r = 0; r < RD; r++) acc[r] = 0.f;
        #pragma unroll 1
        for (int t = 0; t < 8; t++) {
            __syncthreads();
            #pragma unroll
            for (int k = 0; k < 32; k++) {
                int e = tx + k * 256;
                sF[(e >> 4) * FST + (e & 15)] = F[t * 8192 + e];
            }
            __syncthreads();
            #pragma unroll 4
            for (int k = 0; k < 16; k++) {
                int s = lane + k * 32;
                float d = D[(size_t)i * MS + t * 512 + s];
                const float4* f4 = (const float4*)(sF + s * FST);
                float4 f0 = f4[0], f1 = f4[1], f2 = f4[2], f3 = f4[3];
                float dot = f0.x*b[0] + f0.y*b[1] + f0.z*b[2] + f0.w*b[3]
                          + f1.x*b[4] + f1.y*b[5] + f1.z*b[6] + f1.w*b[7]
                          + f2.x*b[8] + f2.y*b[9] + f2.z*b[10] + f2.w*b[11]
                          + f3.x*b[12] + f3.y*b[13] + f3.z*b[14] + f3.w*b[15];
                float rv = (d != 0.f) ? (d - dot) : 0.f;
                float pc = fminf(fmaxf(rv, -thr), thr);
                acc[0]+=f0.x*pc;  acc[1]+=f0.y*pc;  acc[2]+=f0.z*pc;  acc[3]+=f0.w*pc;
                acc[4]+=f1.x*pc;  acc[5]+=f1.y*pc;  acc[6]+=f1.z*pc;  acc[7]+=f1.w*pc;
                acc[8]+=f2.x*pc;  acc[9]+=f2.y*pc;  acc[10]+=f2.z*pc; acc[11]+=f2.w*pc;
                acc[12]+=f3.x*pc; acc[13]+=f3.y*pc; acc[14]+=f3.z*pc; acc[15]+=f3.w*pc;
            }
        }
        #pragma unroll
        for (int r = 0; r < RD; r++) {
            #pragma unroll
            for (int off = 16; off; off >>= 1)
                acc[r] += __shfl_xor_sync(~0u, acc[r], off);
        }
        float delta = 0.f;
        if (lane < 16) {
            const float4* Ai = (const float4*)(g_Ainv + (size_t)i * 256 + lane * 16);
            #pragma unroll
            for (int q = 0; q < 4; q++) {
                float4 a4 = Ai[q];
                delta += a4.x*acc[q*4] + a4.y*acc[q*4+1] + a4.z*acc[q*4+2] + a4.w*acc[q*4+3];
            }
        }
        #pragma unroll
        for (int r = 0; r < RD; r++)
            b[r] += ml * __shfl_sync(~0u, delta, r);
    }

    if (lane < 16) B[i * RD + lane] = b[lane];
}

// ---------------- final out = U @ V ----------------
__global__ void k_out(float* __restrict__ out) {
    __shared__ float sU[64 * RD];
    int tx = threadIdx.x;
    int n = blockIdx.x * 256 + tx;
    int m0 = blockIdx.y * 64;
    #pragma unroll
    for (int k = 0; k < 4; k++)
        sU[tx + k * 256] = g_U[m0 * RD + tx + k * 256];
    float v[RD];
    #pragma unroll
    for (int r = 0; r < RD; r++) v[r] = g_Vt[n * RD + r];
    __syncthreads();
    for (int j = 0; j < 64; j++) {
        float dot = 0.f;
        #pragma unroll
        for (int r = 0; r < RD; r++) dot += sU[j * RD + r] * v[r];
        out[(size_t)(m0 + j) * MS + n] = dot;
    }
}

// ---------------- orchestration ----------------
extern "C" void kernel_launch(void* const* d_in, const int* in_sizes, int n_in,
                              void* d_out, int out_size) {
    const float* U_in  = (const float*)d_in[0];
    const float* V_in  = (const float*)d_in[1];
    const float* X     = (const float*)d_in[2];
    const float* c_in  = (const float*)d_in[3];
    const float* l_in  = (const float*)d_in[4];
    const float* m_in  = (const float*)d_in[5];
    const float* sg_in = (const float*)d_in[6];
    float* out = (float*)d_out;

    float* Xt;   { void* p; cudaGetSymbolAddress(&p, g_Xt); Xt = (float*)p; }
    float* cntc; { void* p; cudaGetSymbolAddress(&p, g_cntc); cntc = (float*)p; }
    float* cntr; { void* p; cudaGetSymbolAddress(&p, g_cntr); cntr = (float*)p; }

    cudaFuncSetAttribute(k_gram, cudaFuncAttributeMaxDynamicSharedMemorySize, GSM);

    dim3 b256(256);
    dim3 ggram(32, KSPLIT);
    dim3 gP(16, 4);

    // order chosen so k_gram is launch index 3 (ncu capture window)
    k_setup<<<256, 256>>>(U_in, V_in);
    k_transpose<<<dim3(128, 128), dim3(32, 8)>>>(X);
    k_P<<<gP, b256>>>(0, 1, c_in, l_in, m_in, 0);
    k_gram<<<ggram, b256, GSM>>>(Xt);          // layer0 V-step gram (profiled)
    k_cnt<<<512, 256>>>(X, cntr);
    k_cnt<<<512, 256>>>(Xt, cntc);
    k_inv<<<4096, 256>>>();
    k_hubreg<<<512, 256>>>(Xt, 0, sg_in);

    // layer0 U step
    k_P<<<gP, b256>>>(1, 0, c_in, l_in, m_in, 0);
    k_gram<<<ggram, b256, GSM>>>(X);
    k_inv<<<4096, 256>>>();
    k_hubreg<<<512, 256>>>(X, 1, sg_in);

    for (int layer = 1; layer < 3; layer++) {
        k_P<<<gP, b256>>>(0, 1, c_in, l_in, m_in, layer);
        k_gram<<<ggram, b256, GSM>>>(Xt);
        k_inv<<<4096, 256>>>();
        k_hubreg<<<512, 256>>>(Xt, 0, sg_in);

        k_P<<<gP, b256>>>(1, 0, c_in, l_in, m_in, layer);
        k_gram<<<ggram, b256, GSM>>>(X);
        k_inv<<<4096, 256>>>();
        k_hubreg<<<512, 256>>>(X, 1, sg_in);
    }

    k_out<<<dim3(16, 64), 256>>>(out);
}

// round 9
// speedup vs baseline: 1.8541x; 1.1553x over previous
#include <cuda_runtime.h>
#include <math.h>
#include <stdint.h>

#define MS 4096            // square: M == N == 4096
#define RD 16
#define NP 136             // 16*17/2 symmetric pairs
#define KSPLIT 8           // split-K for gram
#define EPSR 1e-5f
#define AST 36             // smem row stride (floats) for mma tiles
#define FST 20             // smem row stride for hubreg F staging

// gram smem layout (bytes)
#define GA0 0
#define GA1 18432
#define GB0 36864
#define GB1 56448
#define GSM 76032

// ---------------- scratch (~90 MB of device globals) ----------------
__device__ float g_Xt[(size_t)MS * MS];              // 64 MB  X transposed
__device__ float g_Apart[(size_t)KSPLIT * MS * NP];  // 17.8 MB gram partials [sp][i][p]
__device__ float g_Ainv[(size_t)MS * RD * RD];       // 4.0 MB
__device__ float g_Pt[(size_t)NP * MS];              // 2.2 MB Pt [p][s] (tf32 values)
__device__ float g_U[MS * RD];
__device__ float g_Vt[MS * RD];                      // V transposed: [n][r]
__device__ float g_cntc[MS];
__device__ float g_cntr[MS];
__device__ float g_coef[4];                          // c, lamda, mu, alpha

__device__ __forceinline__ uint32_t smem_u32(const void* p) {
    uint32_t a;
    asm("{ .reg .u64 t; cvta.to.shared.u64 t, %1; cvt.u32.u64 %0, t; }" : "=r"(a) : "l"(p));
    return a;
}
#define CPA16(dst, src) \
    asm volatile("cp.async.ca.shared.global [%0], [%1], 16;" :: "r"(dst), "l"(src))
#define CPA_COMMIT() asm volatile("cp.async.commit_group;" ::: "memory")
#define CPA_WAIT1()  asm volatile("cp.async.wait_group 1;" ::: "memory")
#define CPA_WAIT0()  asm volatile("cp.async.wait_group 0;" ::: "memory")

// ---------------- setup: copy U, transpose V ----------------
__global__ void k_setup(const float* __restrict__ U, const float* __restrict__ V) {
    int tid = blockIdx.x * 256 + threadIdx.x;
    g_U[tid] = U[tid];
    int n = tid >> 4, r = tid & 15;
    g_Vt[tid] = V[r * MS + n];
}

// ---------------- X transpose (32x32 tiles) ----------------
__global__ void k_transpose(const float* __restrict__ X) {
    __shared__ float tile[32][33];
    int x = blockIdx.x * 32 + threadIdx.x;
    int y0 = blockIdx.y * 32;
    #pragma unroll
    for (int j = threadIdx.y; j < 32; j += 8)
        tile[j][threadIdx.x] = X[(size_t)(y0 + j) * MS + x];
    __syncthreads();
    int xo = blockIdx.y * 32 + threadIdx.x;
    int yo0 = blockIdx.x * 32;
    #pragma unroll
    for (int j = threadIdx.y; j < 32; j += 8)
        g_Xt[(size_t)(yo0 + j) * MS + xo] = tile[threadIdx.x][j];
}

// ---------------- row-style counts (warp per row of D) ----------------
__global__ void k_cnt(const float* __restrict__ D, float* __restrict__ cnt) {
    int wid = threadIdx.x >> 5, lane = threadIdx.x & 31;
    int i = blockIdx.x * 8 + wid;
    float c = 0.f;
    for (int s = lane; s < MS; s += 32)
        c += (D[(size_t)i * MS + s] != 0.f) ? 1.f : 0.f;
    #pragma unroll
    for (int off = 16; off; off >>= 1) c += __shfl_xor_sync(~0u, c, off);
    if (lane == 0) cnt[i] = c;
}

// ---------------- P build, p-split over blockIdx.y (+ coefficients) ----------------
__global__ void k_P(int mode, int do_coef, const float* __restrict__ cc,
                    const float* __restrict__ lam, const float* __restrict__ mu, int layer) {
    if (do_coef && blockIdx.x == 0 && blockIdx.y == 0 && threadIdx.x == 0) {
        double cl = (double)cc[layer];
        double chi1 = erf(sqrt(cl));
        double y = 0.5 * cl * cl;
        double chi3 = erf(sqrt(y)) - 2.0 * sqrt(y) * exp(-y) / sqrt(3.14159265358979323846);
        double alpha = cl * (1.0 - chi1) + 0.5 * chi3;
        g_coef[0] = (float)cl;
        g_coef[1] = lam[layer];
        g_coef[2] = mu[layer];
        g_coef[3] = (float)alpha;
    }
    int s = blockIdx.x * 256 + threadIdx.x;
    int plo = blockIdx.y * 34, phi = plo + 34;
    const float* F = mode ? g_Vt : g_U;
    float u[RD];
    const float4* f4 = (const float4*)(F + s * RD);
    #pragma unroll
    for (int q = 0; q < 4; q++) {
        float4 v = f4[q];
        u[q * 4 + 0] = v.x; u[q * 4 + 1] = v.y; u[q * 4 + 2] = v.z; u[q * 4 + 3] = v.w;
    }
    #pragma unroll
    for (int r = 0; r < RD; r++) {
        #pragma unroll
        for (int c2 = 0; c2 <= r; c2++) {
            int pidx = r * (r + 1) / 2 + c2;
            if (pidx >= plo && pidx < phi) {
                float v = u[r] * u[c2];
                uint32_t t;
                asm("cvt.rna.tf32.f32 %0, %1;" : "=r"(t) : "f"(v));
                g_Pt[(size_t)pidx * MS + s] = __uint_as_float(t);
            }
        }
    }
}

// ---------------- tf32 mma.sync Gram with cp.async double buffering ----------------
__device__ __forceinline__ void mma_tf32(float* c, const uint32_t* a, uint32_t b0, uint32_t b1) {
    asm volatile(
        "mma.sync.aligned.m16n8k8.row.col.f32.tf32.tf32.f32 "
        "{%0,%1,%2,%3}, {%4,%5,%6,%7}, {%8,%9}, {%0,%1,%2,%3};"
        : "+f"(c[0]), "+f"(c[1]), "+f"(c[2]), "+f"(c[3])
        : "r"(a[0]), "r"(a[1]), "r"(a[2]), "r"(a[3]), "r"(b0), "r"(b1));
}

__global__ __launch_bounds__(256, 2) void k_gram(const float* __restrict__ D) {
    extern __shared__ char sm[];
    uint32_t sb = smem_u32(sm);
    int tx = threadIdx.x, wid = tx >> 5, lane = tx & 31;
    int g = lane >> 2, tig = lane & 3;
    int wm = wid & 3, wn = wid >> 2;
    int j0 = blockIdx.x * 128;
    int sbase = blockIdx.y * (MS / KSPLIT);
    int nbase = wn * 9;
    int ntiles = wn ? 8 : 9;
    const int NCH = (MS / KSPLIT) / 32;   // 16 chunks

    auto issue = [&](int ch, int b) {
        int s0 = sbase + ch * 32;
        uint32_t ab = sb + (b ? GA1 : GA0);
        uint32_t bb = sb + (b ? GB1 : GB0);
        int rA = tx >> 3, s4 = (tx & 7) * 4;
        #pragma unroll
        for (int k = 0; k < 4; k++) {
            int row = rA + k * 32;
            CPA16(ab + row * (AST * 4) + s4 * 4,
                  D + (size_t)(j0 + row) * MS + s0 + s4);
        }
        #pragma unroll
        for (int k = 0; k < 5; k++) {
            int e = tx + k * 256;
            int row = e >> 3, sb4 = (e & 7) * 4;
            if (row < NP)
                CPA16(bb + row * (AST * 4) + sb4 * 4,
                      g_Pt + (size_t)row * MS + s0 + sb4);
        }
        CPA_COMMIT();
    };

    float c[2][9][4];
    #pragma unroll
    for (int tm = 0; tm < 2; tm++)
        #pragma unroll
        for (int nt = 0; nt < 9; nt++)
            #pragma unroll
            for (int q = 0; q < 4; q++) c[tm][nt][q] = 0.f;

    issue(0, 0);
    for (int ch = 0; ch < NCH; ch++) {
        if (ch + 1 < NCH) { issue(ch + 1, (ch + 1) & 1); CPA_WAIT1(); }
        else              { CPA_WAIT0(); }
        __syncthreads();
        const float* As = (const float*)(sm + ((ch & 1) ? GA1 : GA0));
        const float* Bs = (const float*)(sm + ((ch & 1) ? GB1 : GB0));

        #pragma unroll
        for (int t = 0; t < 4; t++) {
            int kc = t * 8;
            uint32_t a[2][4];
            #pragma unroll
            for (int tm = 0; tm < 2; tm++) {
                int r0 = wm * 32 + tm * 16;
                float x0 = As[(r0 + g) * AST + kc + tig];
                float x1 = As[(r0 + g + 8) * AST + kc + tig];
                float x2 = As[(r0 + g) * AST + kc + tig + 4];
                float x3 = As[(r0 + g + 8) * AST + kc + tig + 4];
                a[tm][0] = (x0 != 0.f) ? 0x3F800000u : 0u;
                a[tm][1] = (x1 != 0.f) ? 0x3F800000u : 0u;
                a[tm][2] = (x2 != 0.f) ? 0x3F800000u : 0u;
                a[tm][3] = (x3 != 0.f) ? 0x3F800000u : 0u;
            }
            #pragma unroll
            for (int nt = 0; nt < 9; nt++) {
                if (nt < ntiles) {
                    int n0 = (nbase + nt) * 8;
                    uint32_t b0 = __float_as_uint(Bs[(n0 + g) * AST + kc + tig]);
                    uint32_t b1 = __float_as_uint(Bs[(n0 + g) * AST + kc + tig + 4]);
                    mma_tf32(c[0][nt], a[0], b0, b1);
                    mma_tf32(c[1][nt], a[1], b0, b1);
                }
            }
        }
        __syncthreads();
    }

    // epilogue: Apart[sp][i][p] (i-major -> coalesced inversion reads)
    #pragma unroll
    for (int tm = 0; tm < 2; tm++) {
        int row = j0 + wm * 32 + tm * 16 + g;
        float* d0 = g_Apart + ((size_t)blockIdx.y * MS + row) * NP;
        float* d1 = g_Apart + ((size_t)blockIdx.y * MS + row + 8) * NP;
        #pragma unroll
        for (int nt = 0; nt < 9; nt++) {
            if (nt < ntiles) {
                int p0 = (nbase + nt) * 8 + 2 * tig;
                d0[p0]     = c[tm][nt][0];
                d0[p0 + 1] = c[tm][nt][1];
                d1[p0]     = c[tm][nt][2];
                d1[p0 + 1] = c[tm][nt][3];
            }
        }
    }
}

// ---------------- warp-per-matrix Gauss-Jordan inversion (no barriers) ----------------
__global__ __launch_bounds__(256) void k_inv() {
    __shared__ float sA[8][144];
    int tx = threadIdx.x, wid = tx >> 5, lane = tx & 31;
    int i = blockIdx.x * 8 + wid;

    // coalesced split-K reduction: lane reads p = lane, lane+32, ...
    float part[5];
    #pragma unroll
    for (int q = 0; q < 5; q++) part[q] = 0.f;
    #pragma unroll
    for (int sp = 0; sp < KSPLIT; sp++) {
        const float* src = g_Apart + ((size_t)sp * MS + i) * NP;
        #pragma unroll
        for (int q = 0; q < 5; q++) {
            int p = lane + q * 32;
            if (p < NP) part[q] += src[p];
        }
    }
    #pragma unroll
    for (int q = 0; q < 5; q++) {
        int p = lane + q * 32;
        if (p < NP) sA[wid][p] = part[q];
    }
    __syncwarp();

    // lane (r, h): holds M[r][8h..8h+7] and Inv[r][8h..8h+7]
    int r = lane >> 1, h = lane & 1;
    float a[8], v[8];
    #pragma unroll
    for (int j = 0; j < 8; j++) {
        int cc = 8 * h + j;
        int rr = max(r, cc), cs = min(r, cc);
        a[j] = sA[wid][rr * (rr + 1) / 2 + cs] + ((r == cc) ? EPSR : 0.f);
        v[j] = (cc == r) ? 1.f : 0.f;
    }

    #pragma unroll
    for (int k = 0; k < 16; k++) {
        const int kh = k >> 3, kc = k & 7;
        float piv = __shfl_sync(~0u, a[kc], 2 * k + kh);   // M[k][k]
        float f   = __shfl_sync(~0u, a[kc], 2 * r + kh);   // M[r][k]
        float pa[8], pv[8];
        #pragma unroll
        for (int j = 0; j < 8; j++) {
            pa[j] = __shfl_sync(~0u, a[j], 2 * k + h);     // pivot row, my half
            pv[j] = __shfl_sync(~0u, v[j], 2 * k + h);
        }
        float ip = 1.f / piv;
        if (r == k) {
            #pragma unroll
            for (int j = 0; j < 8; j++) { a[j] *= ip; v[j] *= ip; }
        } else {
            float fi = f * ip;
            #pragma unroll
            for (int j = 0; j < 8; j++) { a[j] -= fi * pa[j]; v[j] -= fi * pv[j]; }
        }
    }

    float* dst = g_Ainv + (size_t)i * 256 + r * 16 + 8 * h;
    #pragma unroll
    for (int j = 0; j < 8; j++) dst[j] = v[j];
}

// ---------------- fully fused hubreg: warp per item, both iterations ----------------
__global__ __launch_bounds__(256) void k_hubreg(const float* __restrict__ D, int mode,
                                                const float* __restrict__ sg_in) {
    __shared__ float sF[512 * FST];
    int tx = threadIdx.x, wid = tx >> 5, lane = tx & 31;
    int i = blockIdx.x * 8 + wid;
    const float* F = mode ? g_Vt : g_U;
    float* B = mode ? g_U : g_Vt;
    float cnt = (mode ? g_cntr : g_cntc)[i];
    float cl = g_coef[0], ll = g_coef[1], ml = g_coef[2], alpha = g_coef[3];
    float denom = rsqrtf(2.f * cnt * alpha);

    float b[RD];
    #pragma unroll
    for (int q = 0; q < 4; q++) {
        float4 v = ((const float4*)(B + i * RD))[q];
        b[q*4+0]=v.x; b[q*4+1]=v.y; b[q*4+2]=v.z; b[q*4+3]=v.w;
    }
    float sg = sg_in[0];

    #pragma unroll 1
    for (int iter = 0; iter < 2; iter++) {
        float inv_sg = 1.f / sg;
        float ssq = 0.f;
        #pragma unroll 1
        for (int t = 0; t < 8; t++) {
            __syncthreads();
            #pragma unroll
            for (int k = 0; k < 32; k++) {
                int e = tx + k * 256;
                sF[(e >> 4) * FST + (e & 15)] = F[t * 8192 + e];
            }
            __syncthreads();
            #pragma unroll 4
            for (int k = 0; k < 16; k++) {
                int s = lane + k * 32;
                float d = D[(size_t)i * MS + t * 512 + s];
                const float4* f4 = (const float4*)(sF + s * FST);
                float dot = 0.f;
                #pragma unroll
                for (int q = 0; q < 4; q++) {
                    float4 f = f4[q];
                    dot += f.x*b[q*4] + f.y*b[q*4+1] + f.z*b[q*4+2] + f.w*b[q*4+3];
                }
                float rv = (d != 0.f) ? (d - dot) : 0.f;
                float ps = fminf(fmaxf(rv * inv_sg, -cl), cl);
                ssq += ps * ps;
            }
        }
        #pragma unroll
        for (int off = 16; off; off >>= 1) ssq += __shfl_xor_sync(~0u, ssq, off);
        sg = ll * sqrtf(ssq) * denom;
        float thr = cl * sg;

        float acc[RD];
        #pragma unroll
        for (int r = 0; r < RD; r++) acc[r] = 0.f;
        #pragma unroll 1
        for (int t = 0; t < 8; t++) {
            __syncthreads();
            #pragma unroll
            for (int k = 0; k < 32; k++) {
                int e = tx + k * 256;
                sF[(e >> 4) * FST + (e & 15)] = F[t * 8192 + e];
            }
            __syncthreads();
            #pragma unroll 4
            for (int k = 0; k < 16; k++) {
                int s = lane + k * 32;
                float d = D[(size_t)i * MS + t * 512 + s];
                const float4* f4 = (const float4*)(sF + s * FST);
                float4 f0 = f4[0], f1 = f4[1], f2 = f4[2], f3 = f4[3];
                float dot = f0.x*b[0] + f0.y*b[1] + f0.z*b[2] + f0.w*b[3]
                          + f1.x*b[4] + f1.y*b[5] + f1.z*b[6] + f1.w*b[7]
                          + f2.x*b[8] + f2.y*b[9] + f2.z*b[10] + f2.w*b[11]
                          + f3.x*b[12] + f3.y*b[13] + f3.z*b[14] + f3.w*b[15];
                float rv = (d != 0.f) ? (d - dot) : 0.f;
                float pc = fminf(fmaxf(rv, -thr), thr);
                acc[0]+=f0.x*pc;  acc[1]+=f0.y*pc;  acc[2]+=f0.z*pc;  acc[3]+=f0.w*pc;
                acc[4]+=f1.x*pc;  acc[5]+=f1.y*pc;  acc[6]+=f1.z*pc;  acc[7]+=f1.w*pc;
                acc[8]+=f2.x*pc;  acc[9]+=f2.y*pc;  acc[10]+=f2.z*pc; acc[11]+=f2.w*pc;
                acc[12]+=f3.x*pc; acc[13]+=f3.y*pc; acc[14]+=f3.z*pc; acc[15]+=f3.w*pc;
            }
        }
        #pragma unroll
        for (int r = 0; r < RD; r++) {
            #pragma unroll
            for (int off = 16; off; off >>= 1)
                acc[r] += __shfl_xor_sync(~0u, acc[r], off);
        }
        float delta = 0.f;
        if (lane < 16) {
            const float4* Ai = (const float4*)(g_Ainv + (size_t)i * 256 + lane * 16);
            #pragma unroll
            for (int q = 0; q < 4; q++) {
                float4 a4 = Ai[q];
                delta += a4.x*acc[q*4] + a4.y*acc[q*4+1] + a4.z*acc[q*4+2] + a4.w*acc[q*4+3];
            }
        }
        #pragma unroll
        for (int r = 0; r < RD; r++)
            b[r] += ml * __shfl_sync(~0u, delta, r);
    }

    if (lane < 16) B[i * RD + lane] = b[lane];
}

// ---------------- final out = U @ V ----------------
__global__ void k_out(float* __restrict__ out) {
    __shared__ float sU[64 * RD];
    int tx = threadIdx.x;
    int n = blockIdx.x * 256 + tx;
    int m0 = blockIdx.y * 64;
    #pragma unroll
    for (int k = 0; k < 4; k++)
        sU[tx + k * 256] = g_U[m0 * RD + tx + k * 256];
    float v[RD];
    #pragma unroll
    for (int r = 0; r < RD; r++) v[r] = g_Vt[n * RD + r];
    __syncthreads();
    for (int j = 0; j < 64; j++) {
        float dot = 0.f;
        #pragma unroll
        for (int r = 0; r < RD; r++) dot += sU[j * RD + r] * v[r];
        out[(size_t)(m0 + j) * MS + n] = dot;
    }
}

// ---------------- orchestration ----------------
extern "C" void kernel_launch(void* const* d_in, const int* in_sizes, int n_in,
                              void* d_out, int out_size) {
    const float* U_in  = (const float*)d_in[0];
    const float* V_in  = (const float*)d_in[1];
    const float* X     = (const float*)d_in[2];
    const float* c_in  = (const float*)d_in[3];
    const float* l_in  = (const float*)d_in[4];
    const float* m_in  = (const float*)d_in[5];
    const float* sg_in = (const float*)d_in[6];
    float* out = (float*)d_out;

    float* Xt;   { void* p; cudaGetSymbolAddress(&p, g_Xt); Xt = (float*)p; }
    float* cntc; { void* p; cudaGetSymbolAddress(&p, g_cntc); cntc = (float*)p; }
    float* cntr; { void* p; cudaGetSymbolAddress(&p, g_cntr); cntr = (float*)p; }

    cudaFuncSetAttribute(k_gram, cudaFuncAttributeMaxDynamicSharedMemorySize, GSM);

    dim3 b256(256);
    dim3 ggram(32, KSPLIT);
    dim3 gP(16, 4);

    // order chosen so k_gram is launch index 3 (ncu capture window)
    k_setup<<<256, 256>>>(U_in, V_in);
    k_transpose<<<dim3(128, 128), dim3(32, 8)>>>(X);
    k_P<<<gP, b256>>>(0, 1, c_in, l_in, m_in, 0);
    k_gram<<<ggram, b256, GSM>>>(Xt);          // layer0 V-step gram (profiled)
    k_cnt<<<512, 256>>>(X, cntr);
    k_cnt<<<512, 256>>>(Xt, cntc);
    k_inv<<<512, 256>>>();
    k_hubreg<<<512, 256>>>(Xt, 0, sg_in);

    // layer0 U step
    k_P<<<gP, b256>>>(1, 0, c_in, l_in, m_in, 0);
    k_gram<<<ggram, b256, GSM>>>(X);
    k_inv<<<512, 256>>>();
    k_hubreg<<<512, 256>>>(X, 1, sg_in);

    for (int layer = 1; layer < 3; layer++) {
        k_P<<<gP, b256>>>(0, 1, c_in, l_in, m_in, layer);
        k_gram<<<ggram, b256, GSM>>>(Xt);
        k_inv<<<512, 256>>>();
        k_hubreg<<<512, 256>>>(Xt, 0, sg_in);

        k_P<<<gP, b256>>>(1, 0, c_in, l_in, m_in, layer);
        k_gram<<<ggram, b256, GSM>>>(X);
        k_inv<<<512, 256>>>();
        k_hubreg<<<512, 256>>>(X, 1, sg_in);
    }

    k_out<<<dim3(16, 64), 256>>>(out);
}

// round 10
// speedup vs baseline: 1.8929x; 1.0209x over previous
#include <cuda_runtime.h>
#include <math.h>
#include <stdint.h>

#define MS 4096            // square: M == N == 4096
#define RD 16
#define NP 136             // 16*17/2 symmetric pairs
#define KSPLIT 16          // split-K for gram
#define EPSR 1e-5f
#define AST 36             // smem row stride (floats) for mma tiles
#define PST 18             // float2 stride per pair row in hubreg staging

// gram smem layout (bytes)
#define GA0 0
#define GA1 18432
#define GB0 36864
#define GB1 56448
#define GSM 76032

// ---------------- scratch (~107 MB of device globals) ----------------
__device__ float g_Xt[(size_t)MS * MS];              // 64 MB  X transposed
__device__ float g_Apart[(size_t)KSPLIT * MS * NP];  // 35.7 MB gram partials [sp][i][p]
__device__ float g_Ainv[(size_t)MS * RD * RD];       // 4.0 MB
__device__ float g_Pt[(size_t)NP * MS];              // 2.2 MB Pt [p][s] (tf32 values)
__device__ float g_U[MS * RD];
__device__ float g_Vt[MS * RD];                      // V transposed: [n][r]
__device__ float g_cntc[MS];
__device__ float g_cntr[MS];
__device__ float g_coef[4];                          // c, lamda, mu, alpha

__device__ __forceinline__ uint32_t smem_u32(const void* p) {
    uint32_t a;
    asm("{ .reg .u64 t; cvta.to.shared.u64 t, %1; cvt.u32.u64 %0, t; }" : "=r"(a) : "l"(p));
    return a;
}
#define CPA16(dst, src) \
    asm volatile("cp.async.ca.shared.global [%0], [%1], 16;" :: "r"(dst), "l"(src))
#define CPA_COMMIT() asm volatile("cp.async.commit_group;" ::: "memory")
#define CPA_WAIT1()  asm volatile("cp.async.wait_group 1;" ::: "memory")
#define CPA_WAIT0()  asm volatile("cp.async.wait_group 0;" ::: "memory")

// ---- packed fp32x2 helpers (sm_100+ base family) ----
__device__ __forceinline__ unsigned long long pack2(float lo, float hi) {
    unsigned long long r;
    asm("mov.b64 %0, {%1, %2};" : "=l"(r) : "f"(lo), "f"(hi));
    return r;
}
__device__ __forceinline__ void unpack2(unsigned long long v, float& lo, float& hi) {
    asm("mov.b64 {%0, %1}, %2;" : "=f"(lo), "=f"(hi) : "l"(v));
}
__device__ __forceinline__ void fma2(unsigned long long& d, unsigned long long a,
                                     unsigned long long b) {
    asm("fma.rn.f32x2 %0, %1, %2, %0;" : "+l"(d) : "l"(a), "l"(b));
}

// ---------------- setup: copy U, transpose V ----------------
__global__ void k_setup(const float* __restrict__ U, const float* __restrict__ V) {
    int tid = blockIdx.x * 256 + threadIdx.x;
    g_U[tid] = U[tid];
    int n = tid >> 4, r = tid & 15;
    g_Vt[tid] = V[r * MS + n];
}

// ---------------- X transpose (32x32 tiles) ----------------
__global__ void k_transpose(const float* __restrict__ X) {
    __shared__ float tile[32][33];
    int x = blockIdx.x * 32 + threadIdx.x;
    int y0 = blockIdx.y * 32;
    #pragma unroll
    for (int j = threadIdx.y; j < 32; j += 8)
        tile[j][threadIdx.x] = X[(size_t)(y0 + j) * MS + x];
    __syncthreads();
    int xo = blockIdx.y * 32 + threadIdx.x;
    int yo0 = blockIdx.x * 32;
    #pragma unroll
    for (int j = threadIdx.y; j < 32; j += 8)
        g_Xt[(size_t)(yo0 + j) * MS + xo] = tile[threadIdx.x][j];
}

// ---------------- row-style counts (warp per row of D) ----------------
__global__ void k_cnt(const float* __restrict__ D, float* __restrict__ cnt) {
    int wid = threadIdx.x >> 5, lane = threadIdx.x & 31;
    int i = blockIdx.x * 8 + wid;
    float c = 0.f;
    for (int s = lane; s < MS; s += 32)
        c += (D[(size_t)i * MS + s] != 0.f) ? 1.f : 0.f;
    #pragma unroll
    for (int off = 16; off; off >>= 1) c += __shfl_xor_sync(~0u, c, off);
    if (lane == 0) cnt[i] = c;
}

// ---------------- P build, p-split over blockIdx.y (+ coefficients) ----------------
__global__ void k_P(int mode, int do_coef, const float* __restrict__ cc,
                    const float* __restrict__ lam, const float* __restrict__ mu, int layer) {
    if (do_coef && blockIdx.x == 0 && blockIdx.y == 0 && threadIdx.x == 0) {
        double cl = (double)cc[layer];
        double chi1 = erf(sqrt(cl));
        double y = 0.5 * cl * cl;
        double chi3 = erf(sqrt(y)) - 2.0 * sqrt(y) * exp(-y) / sqrt(3.14159265358979323846);
        double alpha = cl * (1.0 - chi1) + 0.5 * chi3;
        g_coef[0] = (float)cl;
        g_coef[1] = lam[layer];
        g_coef[2] = mu[layer];
        g_coef[3] = (float)alpha;
    }
    int s = blockIdx.x * 256 + threadIdx.x;
    int plo = blockIdx.y * 34, phi = plo + 34;
    const float* F = mode ? g_Vt : g_U;
    float u[RD];
    const float4* f4 = (const float4*)(F + s * RD);
    #pragma unroll
    for (int q = 0; q < 4; q++) {
        float4 v = f4[q];
        u[q * 4 + 0] = v.x; u[q * 4 + 1] = v.y; u[q * 4 + 2] = v.z; u[q * 4 + 3] = v.w;
    }
    #pragma unroll
    for (int r = 0; r < RD; r++) {
        #pragma unroll
        for (int c2 = 0; c2 <= r; c2++) {
            int pidx = r * (r + 1) / 2 + c2;
            if (pidx >= plo && pidx < phi) {
                float v = u[r] * u[c2];
                uint32_t t;
                asm("cvt.rna.tf32.f32 %0, %1;" : "=r"(t) : "f"(v));
                g_Pt[(size_t)pidx * MS + s] = __uint_as_float(t);
            }
        }
    }
}

// ---------------- tf32 mma.sync Gram with cp.async double buffering ----------------
__device__ __forceinline__ void mma_tf32(float* c, const uint32_t* a, uint32_t b0, uint32_t b1) {
    asm volatile(
        "mma.sync.aligned.m16n8k8.row.col.f32.tf32.tf32.f32 "
        "{%0,%1,%2,%3}, {%4,%5,%6,%7}, {%8,%9}, {%0,%1,%2,%3};"
        : "+f"(c[0]), "+f"(c[1]), "+f"(c[2]), "+f"(c[3])
        : "r"(a[0]), "r"(a[1]), "r"(a[2]), "r"(a[3]), "r"(b0), "r"(b1));
}

__global__ __launch_bounds__(256, 2) void k_gram(const float* __restrict__ D) {
    extern __shared__ char sm[];
    uint32_t sb = smem_u32(sm);
    int tx = threadIdx.x, wid = tx >> 5, lane = tx & 31;
    int g = lane >> 2, tig = lane & 3;
    int wm = wid & 3, wn = wid >> 2;
    int j0 = blockIdx.x * 128;
    int sbase = blockIdx.y * (MS / KSPLIT);
    int nbase = wn * 9;
    int ntiles = wn ? 8 : 9;
    const int NCH = (MS / KSPLIT) / 32;   // 8 chunks

    auto issue = [&](int ch, int b) {
        int s0 = sbase + ch * 32;
        uint32_t ab = sb + (b ? GA1 : GA0);
        uint32_t bb = sb + (b ? GB1 : GB0);
        int rA = tx >> 3, s4 = (tx & 7) * 4;
        #pragma unroll
        for (int k = 0; k < 4; k++) {
            int row = rA + k * 32;
            CPA16(ab + row * (AST * 4) + s4 * 4,
                  D + (size_t)(j0 + row) * MS + s0 + s4);
        }
        #pragma unroll
        for (int k = 0; k < 5; k++) {
            int e = tx + k * 256;
            int row = e >> 3, sb4 = (e & 7) * 4;
            if (row < NP)
                CPA16(bb + row * (AST * 4) + sb4 * 4,
                      g_Pt + (size_t)row * MS + s0 + sb4);
        }
        CPA_COMMIT();
    };

    float c[2][9][4];
    #pragma unroll
    for (int tm = 0; tm < 2; tm++)
        #pragma unroll
        for (int nt = 0; nt < 9; nt++)
            #pragma unroll
            for (int q = 0; q < 4; q++) c[tm][nt][q] = 0.f;

    issue(0, 0);
    for (int ch = 0; ch < NCH; ch++) {
        if (ch + 1 < NCH) { issue(ch + 1, (ch + 1) & 1); CPA_WAIT1(); }
        else              { CPA_WAIT0(); }
        __syncthreads();
        const float* As = (const float*)(sm + ((ch & 1) ? GA1 : GA0));
        const float* Bs = (const float*)(sm + ((ch & 1) ? GB1 : GB0));

        #pragma unroll
        for (int t = 0; t < 4; t++) {
            int kc = t * 8;
            uint32_t a[2][4];
            #pragma unroll
            for (int tm = 0; tm < 2; tm++) {
                int r0 = wm * 32 + tm * 16;
                float x0 = As[(r0 + g) * AST + kc + tig];
                float x1 = As[(r0 + g + 8) * AST + kc + tig];
                float x2 = As[(r0 + g) * AST + kc + tig + 4];
                float x3 = As[(r0 + g + 8) * AST + kc + tig + 4];
                a[tm][0] = (x0 != 0.f) ? 0x3F800000u : 0u;
                a[tm][1] = (x1 != 0.f) ? 0x3F800000u : 0u;
                a[tm][2] = (x2 != 0.f) ? 0x3F800000u : 0u;
                a[tm][3] = (x3 != 0.f) ? 0x3F800000u : 0u;
            }
            #pragma unroll
            for (int nt = 0; nt < 9; nt++) {
                if (nt < ntiles) {
                    int n0 = (nbase + nt) * 8;
                    uint32_t b0 = __float_as_uint(Bs[(n0 + g) * AST + kc + tig]);
                    uint32_t b1 = __float_as_uint(Bs[(n0 + g) * AST + kc + tig + 4]);
                    mma_tf32(c[0][nt], a[0], b0, b1);
                    mma_tf32(c[1][nt], a[1], b0, b1);
                }
            }
        }
        __syncthreads();
    }

    // epilogue: Apart[sp][i][p] (i-major -> coalesced inversion reads)
    #pragma unroll
    for (int tm = 0; tm < 2; tm++) {
        int row = j0 + wm * 32 + tm * 16 + g;
        float* d0 = g_Apart + ((size_t)blockIdx.y * MS + row) * NP;
        float* d1 = g_Apart + ((size_t)blockIdx.y * MS + row + 8) * NP;
        #pragma unroll
        for (int nt = 0; nt < 9; nt++) {
            if (nt < ntiles) {
                int p0 = (nbase + nt) * 8 + 2 * tig;
                d0[p0]     = c[tm][nt][0];
                d0[p0 + 1] = c[tm][nt][1];
                d1[p0]     = c[tm][nt][2];
                d1[p0 + 1] = c[tm][nt][3];
            }
        }
    }
}

// ---------------- warp-per-matrix Gauss-Jordan inversion (no barriers) ----------------
__global__ __launch_bounds__(256) void k_inv() {
    __shared__ float sA[8][144];
    int tx = threadIdx.x, wid = tx >> 5, lane = tx & 31;
    int i = blockIdx.x * 8 + wid;

    float part[5];
    #pragma unroll
    for (int q = 0; q < 5; q++) part[q] = 0.f;
    #pragma unroll
    for (int sp = 0; sp < KSPLIT; sp++) {
        const float* src = g_Apart + ((size_t)sp * MS + i) * NP;
        #pragma unroll
        for (int q = 0; q < 5; q++) {
            int p = lane + q * 32;
            if (p < NP) part[q] += src[p];
        }
    }
    #pragma unroll
    for (int q = 0; q < 5; q++) {
        int p = lane + q * 32;
        if (p < NP) sA[wid][p] = part[q];
    }
    __syncwarp();

    int r = lane >> 1, h = lane & 1;
    float a[8], v[8];
    #pragma unroll
    for (int j = 0; j < 8; j++) {
        int cc = 8 * h + j;
        int rr = max(r, cc), cs = min(r, cc);
        a[j] = sA[wid][rr * (rr + 1) / 2 + cs] + ((r == cc) ? EPSR : 0.f);
        v[j] = (cc == r) ? 1.f : 0.f;
    }

    #pragma unroll
    for (int k = 0; k < 16; k++) {
        const int kh = k >> 3, kc = k & 7;
        float piv = __shfl_sync(~0u, a[kc], 2 * k + kh);
        float f   = __shfl_sync(~0u, a[kc], 2 * r + kh);
        float pa[8], pv[8];
        #pragma unroll
        for (int j = 0; j < 8; j++) {
            pa[j] = __shfl_sync(~0u, a[j], 2 * k + h);
            pv[j] = __shfl_sync(~0u, v[j], 2 * k + h);
        }
        float ip = 1.f / piv;
        if (r == k) {
            #pragma unroll
            for (int j = 0; j < 8; j++) { a[j] *= ip; v[j] *= ip; }
        } else {
            float fi = f * ip;
            #pragma unroll
            for (int j = 0; j < 8; j++) { a[j] -= fi * pa[j]; v[j] -= fi * pv[j]; }
        }
    }

    float* dst = g_Ainv + (size_t)i * 256 + r * 16 + 8 * h;
    #pragma unroll
    for (int j = 0; j < 8; j++) dst[j] = v[j];
}

// ---------------- fused hubreg with packed f32x2 math ----------------
__global__ __launch_bounds__(256) void k_hubreg(const float* __restrict__ D, int mode,
                                                const float* __restrict__ sg_in) {
    __shared__ float2 sF2[256 * PST];    // 36 KB: pair-interleaved F staging
    int tx = threadIdx.x, wid = tx >> 5, lane = tx & 31;
    int i = blockIdx.x * 8 + wid;
    const float* F = mode ? g_Vt : g_U;
    float* B = mode ? g_U : g_Vt;
    float cnt = (mode ? g_cntr : g_cntc)[i];
    float cl = g_coef[0], ll = g_coef[1], ml = g_coef[2], alpha = g_coef[3];
    float denom = rsqrtf(2.f * cnt * alpha);

    float b[RD];
    #pragma unroll
    for (int q = 0; q < 4; q++) {
        float4 v = ((const float4*)(B + i * RD))[q];
        b[q*4+0]=v.x; b[q*4+1]=v.y; b[q*4+2]=v.z; b[q*4+3]=v.w;
    }
    float sg = sg_in[0];

    #pragma unroll 1
    for (int iter = 0; iter < 2; iter++) {
        unsigned long long bp[RD];
        #pragma unroll
        for (int r = 0; r < RD; r++) bp[r] = pack2(b[r], b[r]);

        // ---- sweep A: ssq ----
        float inv_sg = 1.f / sg;
        unsigned long long ssqp = 0ull;
        #pragma unroll 1
        for (int t = 0; t < 8; t++) {
            __syncthreads();
            #pragma unroll
            for (int k = 0; k < 32; k++) {
                int e = tx + k * 256;
                int s = e >> 4, r = e & 15;
                ((float*)sF2)[((s >> 1) * PST + r) * 2 + (s & 1)] = F[t * 8192 + e];
            }
            __syncthreads();
            #pragma unroll 2
            for (int k = 0; k < 8; k++) {
                int p = lane + k * 32;
                float2 d2 = *(const float2*)&D[(size_t)i * MS + t * 512 + 2 * p];
                const ulonglong2* fp = (const ulonglong2*)(sF2 + (size_t)p * PST);
                unsigned long long dotp = 0ull;
                #pragma unroll
                for (int q = 0; q < 8; q++) {
                    ulonglong2 u = fp[q];
                    fma2(dotp, u.x, bp[2 * q]);
                    fma2(dotp, u.y, bp[2 * q + 1]);
                }
                float dl, dh;
                unpack2(dotp, dl, dh);
                float rv0 = (d2.x != 0.f) ? (d2.x - dl) : 0.f;
                float rv1 = (d2.y != 0.f) ? (d2.y - dh) : 0.f;
                float p0 = fminf(fmaxf(rv0 * inv_sg, -cl), cl);
                float p1 = fminf(fmaxf(rv1 * inv_sg, -cl), cl);
                unsigned long long pp = pack2(p0, p1);
                fma2(ssqp, pp, pp);
            }
        }
        float s0, s1;
        unpack2(ssqp, s0, s1);
        float ssq = s0 + s1;
        #pragma unroll
        for (int off = 16; off; off >>= 1) ssq += __shfl_xor_sync(~0u, ssq, off);
        sg = ll * sqrtf(ssq) * denom;
        float thr = cl * sg;

        // ---- sweep B: t accumulation ----
        unsigned long long accp[RD];
        #pragma unroll
        for (int r = 0; r < RD; r++) accp[r] = 0ull;
        #pragma unroll 1
        for (int t = 0; t < 8; t++) {
            __syncthreads();
            #pragma unroll
            for (int k = 0; k < 32; k++) {
                int e = tx + k * 256;
                int s = e >> 4, r = e & 15;
                ((float*)sF2)[((s >> 1) * PST + r) * 2 + (s & 1)] = F[t * 8192 + e];
            }
            __syncthreads();
            #pragma unroll 2
            for (int k = 0; k < 8; k++) {
                int p = lane + k * 32;
                float2 d2 = *(const float2*)&D[(size_t)i * MS + t * 512 + 2 * p];
                const ulonglong2* fp = (const ulonglong2*)(sF2 + (size_t)p * PST);
                ulonglong2 u[8];
                #pragma unroll
                for (int q = 0; q < 8; q++) u[q] = fp[q];
                unsigned long long dotp = 0ull;
                #pragma unroll
                for (int q = 0; q < 8; q++) {
                    fma2(dotp, u[q].x, bp[2 * q]);
                    fma2(dotp, u[q].y, bp[2 * q + 1]);
                }
                float dl, dh;
                unpack2(dotp, dl, dh);
                float rv0 = (d2.x != 0.f) ? (d2.x - dl) : 0.f;
                float rv1 = (d2.y != 0.f) ? (d2.y - dh) : 0.f;
                float pc0 = fminf(fmaxf(rv0, -thr), thr);
                float pc1 = fminf(fmaxf(rv1, -thr), thr);
                unsigned long long pcp = pack2(pc0, pc1);
                #pragma unroll
                for (int q = 0; q < 8; q++) {
                    fma2(accp[2 * q],     u[q].x, pcp);
                    fma2(accp[2 * q + 1], u[q].y, pcp);
                }
            }
        }
        float acc[RD];
        #pragma unroll
        for (int r = 0; r < RD; r++) {
            float lo, hi;
            unpack2(accp[r], lo, hi);
            acc[r] = lo + hi;
        }
        #pragma unroll
        for (int r = 0; r < RD; r++) {
            #pragma unroll
            for (int off = 16; off; off >>= 1)
                acc[r] += __shfl_xor_sync(~0u, acc[r], off);
        }
        float delta = 0.f;
        if (lane < 16) {
            const float4* Ai = (const float4*)(g_Ainv + (size_t)i * 256 + lane * 16);
            #pragma unroll
            for (int q = 0; q < 4; q++) {
                float4 a4 = Ai[q];
                delta += a4.x*acc[q*4] + a4.y*acc[q*4+1] + a4.z*acc[q*4+2] + a4.w*acc[q*4+3];
            }
        }
        #pragma unroll
        for (int r = 0; r < RD; r++)
            b[r] += ml * __shfl_sync(~0u, delta, r);
    }

    if (lane < 16) B[i * RD + lane] = b[lane];
}

// ---------------- final out = U @ V ----------------
__global__ void k_out(float* __restrict__ out) {
    __shared__ float sU[64 * RD];
    int tx = threadIdx.x;
    int n = blockIdx.x * 256 + tx;
    int m0 = blockIdx.y * 64;
    #pragma unroll
    for (int k = 0; k < 4; k++)
        sU[tx + k * 256] = g_U[m0 * RD + tx + k * 256];
    float v[RD];
    #pragma unroll
    for (int r = 0; r < RD; r++) v[r] = g_Vt[n * RD + r];
    __syncthreads();
    for (int j = 0; j < 64; j++) {
        float dot = 0.f;
        #pragma unroll
        for (int r = 0; r < RD; r++) dot += sU[j * RD + r] * v[r];
        out[(size_t)(m0 + j) * MS + n] = dot;
    }
}

// ---------------- orchestration ----------------
extern "C" void kernel_launch(void* const* d_in, const int* in_sizes, int n_in,
                              void* d_out, int out_size) {
    const float* U_in  = (const float*)d_in[0];
    const float* V_in  = (const float*)d_in[1];
    const float* X     = (const float*)d_in[2];
    const float* c_in  = (const float*)d_in[3];
    const float* l_in  = (const float*)d_in[4];
    const float* m_in  = (const float*)d_in[5];
    const float* sg_in = (const float*)d_in[6];
    float* out = (float*)d_out;

    float* Xt;   { void* p; cudaGetSymbolAddress(&p, g_Xt); Xt = (float*)p; }
    float* cntc; { void* p; cudaGetSymbolAddress(&p, g_cntc); cntc = (float*)p; }
    float* cntr; { void* p; cudaGetSymbolAddress(&p, g_cntr); cntr = (float*)p; }

    cudaFuncSetAttribute(k_gram, cudaFuncAttributeMaxDynamicSharedMemorySize, GSM);

    dim3 b256(256);
    dim3 ggram(32, KSPLIT);
    dim3 gP(16, 4);

    // order chosen so k_gram is launch index 3 (ncu capture window)
    k_setup<<<256, 256>>>(U_in, V_in);
    k_transpose<<<dim3(128, 128), dim3(32, 8)>>>(X);
    k_P<<<gP, b256>>>(0, 1, c_in, l_in, m_in, 0);
    k_gram<<<ggram, b256, GSM>>>(Xt);          // layer0 V-step gram (profiled)
    k_cnt<<<512, 256>>>(X, cntr);
    k_cnt<<<512, 256>>>(Xt, cntc);
    k_inv<<<512, 256>>>();
    k_hubreg<<<512, 256>>>(Xt, 0, sg_in);

    // layer0 U step
    k_P<<<gP, b256>>>(1, 0, c_in, l_in, m_in, 0);
    k_gram<<<ggram, b256, GSM>>>(X);
    k_inv<<<512, 256>>>();
    k_hubreg<<<512, 256>>>(X, 1, sg_in);

    for (int layer = 1; layer < 3; layer++) {
        k_P<<<gP, b256>>>(0, 1, c_in, l_in, m_in, layer);
        k_gram<<<ggram, b256, GSM>>>(Xt);
        k_inv<<<512, 256>>>();
        k_hubreg<<<512, 256>>>(Xt, 0, sg_in);

        k_P<<<gP, b256>>>(1, 0, c_in, l_in, m_in, layer);
        k_gram<<<ggram, b256, GSM>>>(X);
        k_inv<<<512, 256>>>();
        k_hubreg<<<512, 256>>>(X, 1, sg_in);
    }

    k_out<<<dim3(16, 64), 256>>>(out);
}